// round 13
// baseline (speedup 1.0000x reference)
#include <cuda_runtime.h>
#include <cuda_bf16.h>
#include <math.h>
#include <stdint.h>

#define NN 4096
#define FF 1433
#define HH 32
#define CC 7
#define EE 131072

// ---------------- device scratch ----------------
__device__ int8_t g_A8[(size_t)NN * NN];
__device__ float g_A1[(size_t)2048 * 2048];
__device__ float g_A2[(size_t)1024 * 1024];
__device__ float g_A3[(size_t)512 * 512];
__device__ float g_part[(size_t)32 * 4096 * 32];
__device__ int   g_rowptr[NN + 1];
__device__ int   g_colidx[2 * EE];
__device__ int   g_deg[NN];
__device__ float g_x0[NN * HH];
__device__ float g_xs0[NN * HH];
__device__ float g_xs1[2048 * HH];
__device__ float g_xs2[1024 * HH];
__device__ float g_hA[NN * HH];
__device__ float g_hB[NN * HH];
__device__ float g_Y[NN * HH];
__device__ float g_dinv[8192];
__device__ int   g_perm[NN];

#define S8STRIDE 144
#define ASTRIDE 36
#define CSTRIDE 129
#define BUFSZ 18432
#define AUG_SMEM (4 * BUFSZ + 1536)

#define CP_ASYNC16(dst, src) \
    asm volatile("cp.async.cg.shared.global [%0], [%1], 16;" :: "r"(dst), "l"(src))
#define CP_COMMIT() asm volatile("cp.async.commit_group;" ::: "memory")
#define CP_WAIT(n)  asm volatile("cp.async.wait_group %0;" :: "n"(n) : "memory")

// ---------------- level-0 sparse path ----------------

__global__ void scatter_edges_k(const int* __restrict__ ei, int8_t* __restrict__ A8) {
    int e = blockIdx.x * blockDim.x + threadIdx.x;
    if (e < EE) {
        int u = ei[e], v = ei[EE + e];
        if (u != v) {
            A8[(size_t)u * NN + v] = 1;
            A8[(size_t)v * NN + u] = 1;
        }
    }
}

__global__ void degree_dinv_k(const int8_t* __restrict__ A8, int* __restrict__ deg,
                              float* __restrict__ dinv) {
    int warp = (blockIdx.x * blockDim.x + threadIdx.x) >> 5;
    int lane = threadIdx.x & 31;
    if (warp >= NN) return;
    const uchar4* row = (const uchar4*)&A8[(size_t)warp * NN];
    int cnt = 0;
    for (int it = lane; it < NN / 4; it += 32) {
        uchar4 v = row[it];
        cnt += (v.x != 0) + (v.y != 0) + (v.z != 0) + (v.w != 0);
    }
#pragma unroll
    for (int o = 16; o > 0; o >>= 1) cnt += __shfl_down_sync(0xffffffffu, cnt, o);
    if (lane == 0) {
        deg[warp] = cnt;
        dinv[warp] = rsqrtf((float)cnt + 2.0f);
    }
}

__global__ void prefix_k(const int* __restrict__ deg, int* __restrict__ rowptr) {
    __shared__ int part[1024];
    int tid = threadIdx.x;
    int base = tid * 4;
    int d0 = deg[base], d1 = deg[base + 1], d2 = deg[base + 2], d3 = deg[base + 3];
    int s = d0 + d1 + d2 + d3;
    part[tid] = s;
    __syncthreads();
    for (int o = 1; o < 1024; o <<= 1) {
        int v = (tid >= o) ? part[tid - o] : 0;
        __syncthreads();
        part[tid] += v;
        __syncthreads();
    }
    int excl = (tid == 0) ? 0 : part[tid - 1];
    rowptr[base]     = excl;
    rowptr[base + 1] = excl + d0;
    rowptr[base + 2] = excl + d0 + d1;
    rowptr[base + 3] = excl + d0 + d1 + d2;
    if (tid == 1023) rowptr[4096] = part[1023];
}

__global__ void csr_fill_k(const int8_t* __restrict__ A8, const int* __restrict__ rowptr,
                           int* __restrict__ colidx) {
    int warp = (blockIdx.x * blockDim.x + threadIdx.x) >> 5;
    int lane = threadIdx.x & 31;
    if (warp >= NN) return;
    const int8_t* row = &A8[(size_t)warp * NN];
    int pos = rowptr[warp];
    for (int c0 = 0; c0 < NN; c0 += 128) {
        uint32_t w = *(const uint32_t*)&row[c0 + lane * 4];
        int b0 = (w & 0xffu) != 0, b1 = (w & 0xff00u) != 0;
        int b2 = (w & 0xff0000u) != 0, b3 = (w & 0xff000000u) != 0;
        int cnt = b0 + b1 + b2 + b3;
        int inc = cnt;
#pragma unroll
        for (int o = 1; o < 32; o <<= 1) {
            int v = __shfl_up_sync(0xffffffffu, inc, o);
            if (lane >= o) inc += v;
        }
        int excl = inc - cnt;
        int total = __shfl_sync(0xffffffffu, inc, 31);
        int wr = pos + excl;
        int cb = c0 + lane * 4;
        if (b0) colidx[wr++] = cb;
        if (b1) colidx[wr++] = cb + 1;
        if (b2) colidx[wr++] = cb + 2;
        if (b3) colidx[wr++] = cb + 3;
        pos += total;
    }
}

__global__ void spmm_gcn_k(const int* __restrict__ rowptr, const int* __restrict__ colidx,
                           const float* __restrict__ Y, const float* __restrict__ dinv,
                           const float* __restrict__ bias, float* __restrict__ out,
                           int N, int relu) {
    int warp = (blockIdx.x * blockDim.x + threadIdx.x) >> 5;
    int lane = threadIdx.x & 31;
    if (warp >= NN) return;
    int s = rowptr[warp], e = rowptr[warp + 1];
    float acc = 0.f;
    bool act = lane < N;
    for (int base = s; base < e; base += 32) {
        int idx = (base + lane < e) ? colidx[base + lane] : 0;
        int cnt = min(32, e - base);
        int t = 0;
        for (; t + 8 <= cnt; t += 8) {
            float v[8];
#pragma unroll
            for (int q = 0; q < 8; q++) {
                int j = __shfl_sync(0xffffffffu, idx, t + q);
                v[q] = act ? dinv[j] * Y[(size_t)j * N + lane] : 0.f;
            }
#pragma unroll
            for (int q = 0; q < 8; q++) acc += v[q];
        }
        for (; t < cnt; t++) {
            int j = __shfl_sync(0xffffffffu, idx, t);
            if (act) acc += dinv[j] * Y[(size_t)j * N + lane];
        }
    }
    if (act) {
        float dr = dinv[warp];
        float v = dr * (acc + 2.0f * dr * Y[(size_t)warp * N + lane]) + bias[lane];
        if (relu) v = fmaxf(v, 0.0f);
        out[(size_t)warp * N + lane] = v;
    }
}

// ---------------- fused score + top-k sort + gather ----------------
__global__ void score_sort_gather_k(const float* __restrict__ h, const float* __restrict__ p,
                                    int n, int k, int* __restrict__ perm,
                                    float* __restrict__ out) {
    __shared__ unsigned long long sk[4096];
    __shared__ float ps[HH];
    __shared__ float pn;
    int tid = threadIdx.x;
    if (tid < HH) ps[tid] = p[tid];
    __syncthreads();
    if (tid == 0) {
        float s = 0.f;
        for (int i = 0; i < HH; i++) s += ps[i] * ps[i];
        pn = sqrtf(s);
    }
    __syncthreads();
    for (int i = tid; i < n; i += 1024) {
        float s = 0.f;
        const float* hp = h + (size_t)i * HH;
#pragma unroll
        for (int c = 0; c < HH; c++) s += hp[c] * ps[c];
        float sc = tanhf(s / pn);
        unsigned u = __float_as_uint(sc);
        u = (u & 0x80000000u) ? ~u : (u | 0x80000000u);
        sk[i] = ((unsigned long long)(~u) << 32) | (unsigned)i;
    }
    __syncthreads();
    for (int kk = 2; kk <= n; kk <<= 1) {
        for (int j = kk >> 1; j > 0; j >>= 1) {
            for (int idx = tid; idx < n; idx += 1024) {
                int ixj = idx ^ j;
                if (ixj > idx) {
                    bool up = ((idx & kk) == 0);
                    unsigned long long a = sk[idx], b = sk[ixj];
                    if ((a > b) == up) { sk[idx] = b; sk[ixj] = a; }
                }
            }
            __syncthreads();
        }
    }
    for (int r = tid; r < k; r += 1024) perm[r] = (int)(sk[r] & 0xffffffffULL);
    for (int t = tid; t < k * HH; t += 1024) {
        int r = t >> 5, c = t & 31;
        unsigned long long key = sk[r];
        int pi = (int)(key & 0xffffffffULL);
        unsigned w = ~(unsigned)(key >> 32);
        unsigned ub = (w & 0x80000000u) ? (w & 0x7fffffffu) : ~w;
        out[t] = h[(size_t)pi * HH + c] * __uint_as_float(ub);
    }
}

// ---------------- split-K aggregate GEMM ----------------
#define SAOFF (192 * 32)
#define AGG_SMEM ((192 * 32 + 256 * 33) * 4)

__global__ void __launch_bounds__(256) agg_gemm_k(
    const float* __restrict__ A, const float* __restrict__ B,
    float* __restrict__ part, int M, int N, int K, int Kchunk,
    const float* __restrict__ dinv)
{
    extern __shared__ float sm[];
    float* sB = sm;
    float* sA = sm + SAOFF;

    int tid = threadIdx.x;
    int warp = tid >> 5, lane = tid & 31;
    int myrow = warp * 32 + lane;
    int m0 = blockIdx.x * 256;
    int kc = blockIdx.y * Kchunk;
    bool K4 = (K & 3) == 0;

    for (int i = tid; i < Kchunk * 32; i += 256) {
        int k = i >> 5, c = i & 31;
        int gk = kc + k;
        float bv = 0.f;
        if (gk < K && c < N) {
            bv = B[(size_t)gk * N + c];
            if (dinv) bv *= dinv[gk];
        }
        sB[k * 32 + c] = bv;
    }

    float acc[32];
#pragma unroll
    for (int i = 0; i < 32; i++) acc[i] = 0.f;

    int ksteps = Kchunk >> 5;
    float pv[32];

#define LOADPV(KS) do { \
        int _ks = (KS); \
        _Pragma("unroll") \
        for (int q = 0; q < 8; q++) { \
            int idx = tid + q * 256; \
            int row = idx >> 3, c4 = idx & 7; \
            int gk = kc + _ks * 32 + c4 * 4; \
            const float* ap = &A[(size_t)(m0 + row) * K + gk]; \
            if (K4) { \
                float4 v = (gk < K) ? *(const float4*)ap : make_float4(0, 0, 0, 0); \
                pv[q * 4 + 0] = v.x; pv[q * 4 + 1] = v.y; \
                pv[q * 4 + 2] = v.z; pv[q * 4 + 3] = v.w; \
            } else { \
                _Pragma("unroll") \
                for (int i = 0; i < 4; i++) \
                    pv[q * 4 + i] = (gk + i < K) ? ap[i] : 0.f; \
            } \
        } \
    } while (0)

    LOADPV(0);

    for (int ks = 0; ks < ksteps; ks++) {
        __syncthreads();
#pragma unroll
        for (int q = 0; q < 8; q++) {
            int idx = tid + q * 256;
            int row = idx >> 3, c4 = idx & 7;
#pragma unroll
            for (int i = 0; i < 4; i++)
                sA[row * 33 + c4 * 4 + i] = pv[q * 4 + i];
        }
        __syncthreads();
        if (ks + 1 < ksteps) LOADPV(ks + 1);
#pragma unroll
        for (int kk = 0; kk < 32; kk++) {
            float a = sA[myrow * 33 + kk];
            const float4* bp = (const float4*)&sB[(ks * 32 + kk) * 32];
#pragma unroll
            for (int c4 = 0; c4 < 8; c4++) {
                float4 b = bp[c4];
                acc[c4 * 4 + 0] += a * b.x;
                acc[c4 * 4 + 1] += a * b.y;
                acc[c4 * 4 + 2] += a * b.z;
                acc[c4 * 4 + 3] += a * b.w;
            }
        }
    }

    float* pp = &part[(size_t)blockIdx.y * M * 32 + (size_t)(m0 + myrow) * 32];
#pragma unroll
    for (int c4 = 0; c4 < 8; c4++) {
        float4 v = make_float4(acc[c4 * 4], acc[c4 * 4 + 1], acc[c4 * 4 + 2], acc[c4 * 4 + 3]);
        *(float4*)&pp[c4 * 4] = v;
    }
}

__global__ void agg_reduce_k(const float* __restrict__ part, float* __restrict__ C,
                             const float* __restrict__ Y, const float* __restrict__ dinv,
                             const float* __restrict__ bias, int M, int N, int S,
                             int mode, int relu) {
    int t = blockIdx.x * blockDim.x + threadIdx.x;
    if (t >= M * 32) return;
    int r = t >> 5, c = t & 31;
    float s = 0.f;
    for (int i = 0; i < S; i++) s += part[(size_t)i * M * 32 + t];
    if (c < N) {
        float v = s;
        if (mode == 2) {
            float dr = dinv[r];
            v = dr * (v + 2.0f * dr * Y[(size_t)r * N + c]) + bias[c];
        }
        if (relu) v = fmaxf(v, 0.0f);
        C[(size_t)r * N + c] = v;
    }
}

// ---------------- fused pool+augment with perm-indirect rows ----------------
// A' = Ap[perm][:,perm]^2-ish: C = G@G^T + 2*G[:,perm], G[i] = Ap[perm[i]]

__global__ void __launch_bounds__(256, 2) pool_aug_s8_k(const int8_t* __restrict__ Ap,
                                                        float* __restrict__ C,
                                                        const int* __restrict__ perm,
                                                        int k, int n) {
    extern __shared__ __align__(16) char smem[];
    float* sC = (float*)smem;
    int* spmM = (int*)(smem + 4 * BUFSZ);
    int* spmN = (int*)(smem + 4 * BUFSZ + 512);
    uint32_t sbase = (uint32_t)__cvta_generic_to_shared(smem);

    int tid = threadIdx.x;
    int wid = tid >> 5, lane = tid & 31;
    int wm = wid >> 2, wn = wid & 3;
    int lr = lane >> 2, lc = lane & 3;

    int t = blockIdx.x;
    int by = (int)((sqrtf(8.0f * (float)t + 1.0f) - 1.0f) * 0.5f);
    while ((by + 1) * (by + 2) / 2 <= t) by++;
    while (by * (by + 1) / 2 > t) by--;
    int bx = t - by * (by + 1) / 2;
    int m0 = by * 128, n0 = bx * 128;

    // per-thread loader row perms (4 rows per thread, loop-invariant)
    long prm[4], prn[4];
#pragma unroll
    for (int q = 0; q < 4; q++) {
        int row = (tid + q * 256) >> 3;
        prm[q] = (long)__ldg(&perm[m0 + row]) * n;
        prn[q] = (long)__ldg(&perm[n0 + row]) * n;
    }
    if (tid < 128) {
        spmM[tid] = __ldg(&perm[m0 + tid]);
        spmN[tid] = __ldg(&perm[n0 + tid]);
    }

    int acc[4][4][4];
#pragma unroll
    for (int i = 0; i < 4; i++)
#pragma unroll
        for (int j = 0; j < 4; j++)
#pragma unroll
            for (int q = 0; q < 4; q++) acc[i][j][q] = 0;

    int nch = n >> 7;
#pragma unroll
    for (int q = 0; q < 4; q++) {
        int idx = tid + q * 256;
        int row = idx >> 3, s = idx & 7;
        CP_ASYNC16(sbase + row * S8STRIDE + s * 16, &Ap[prm[q] + s * 16]);
        CP_ASYNC16(sbase + 2 * BUFSZ + row * S8STRIDE + s * 16, &Ap[prn[q] + s * 16]);
    }
    CP_COMMIT();

    for (int ch = 0; ch < nch; ch++) {
        int b = ch & 1;
        if (ch + 1 < nch) {
            int k0 = (ch + 1) << 7;
            int nb = (ch + 1) & 1;
#pragma unroll
            for (int q = 0; q < 4; q++) {
                int idx = tid + q * 256;
                int row = idx >> 3, s = idx & 7;
                CP_ASYNC16(sbase + nb * BUFSZ + row * S8STRIDE + s * 16,
                           &Ap[prm[q] + k0 + s * 16]);
                CP_ASYNC16(sbase + (2 + nb) * BUFSZ + row * S8STRIDE + s * 16,
                           &Ap[prn[q] + k0 + s * 16]);
            }
            CP_COMMIT();
            CP_WAIT(1);
        } else {
            CP_WAIT(0);
        }
        __syncthreads();
        int8_t* sA = (int8_t*)smem + b * BUFSZ;
        int8_t* sB = (int8_t*)smem + (2 + b) * BUFSZ;
#pragma unroll
        for (int kt = 0; kt < 4; kt++) {
            int kk = kt * 32;
            uint32_t a[4][4];
#pragma unroll
            for (int i = 0; i < 4; i++) {
                int r0 = wm * 64 + i * 16;
                a[i][0] = *(const uint32_t*)&sA[(r0 + lr) * S8STRIDE + kk + lc * 4];
                a[i][1] = *(const uint32_t*)&sA[(r0 + lr + 8) * S8STRIDE + kk + lc * 4];
                a[i][2] = *(const uint32_t*)&sA[(r0 + lr) * S8STRIDE + kk + lc * 4 + 16];
                a[i][3] = *(const uint32_t*)&sA[(r0 + lr + 8) * S8STRIDE + kk + lc * 4 + 16];
            }
#pragma unroll
            for (int j = 0; j < 4; j++) {
                int c0 = wn * 32 + j * 8;
                uint32_t b0 = *(const uint32_t*)&sB[(c0 + lr) * S8STRIDE + kk + lc * 4];
                uint32_t b1 = *(const uint32_t*)&sB[(c0 + lr) * S8STRIDE + kk + lc * 4 + 16];
#pragma unroll
                for (int i = 0; i < 4; i++) {
                    asm volatile(
                        "mma.sync.aligned.m16n8k32.row.col.s32.s8.s8.s32 "
                        "{%0,%1,%2,%3}, {%4,%5,%6,%7}, {%8,%9}, {%0,%1,%2,%3};"
                        : "+r"(acc[i][j][0]), "+r"(acc[i][j][1]),
                          "+r"(acc[i][j][2]), "+r"(acc[i][j][3])
                        : "r"(a[i][0]), "r"(a[i][1]), "r"(a[i][2]), "r"(a[i][3]),
                          "r"(b0), "r"(b1));
                }
            }
        }
        __syncthreads();
    }

#pragma unroll
    for (int i = 0; i < 4; i++) {
#pragma unroll
        for (int j = 0; j < 4; j++) {
            int r0 = wm * 64 + i * 16 + lr;
            int c0 = wn * 32 + j * 8 + 2 * lc;
            sC[r0 * CSTRIDE + c0]           = (float)acc[i][j][0];
            sC[r0 * CSTRIDE + c0 + 1]       = (float)acc[i][j][1];
            sC[(r0 + 8) * CSTRIDE + c0]     = (float)acc[i][j][2];
            sC[(r0 + 8) * CSTRIDE + c0 + 1] = (float)acc[i][j][3];
        }
    }
    __syncthreads();

    for (int e = tid; e < 128 * 128; e += 256) {
        int r = e >> 7, c = e & 127;
        float v = sC[r * CSTRIDE + c] +
                  2.0f * (float)Ap[(size_t)spmM[r] * n + spmN[c]];
        if (m0 + r == n0 + c) v = 0.0f;
        C[(size_t)(m0 + r) * k + n0 + c] = v;
        sC[r * CSTRIDE + c] = v;
    }
    __syncthreads();
    if (bx != by) {
        for (int e = tid; e < 128 * 128; e += 256) {
            int r = e >> 7, c = e & 127;
            C[(size_t)(n0 + r) * k + m0 + c] = sC[c * CSTRIDE + r];
        }
    }
}

__global__ void __launch_bounds__(256, 2) pool_aug_tf32_k(const float* __restrict__ Ap,
                                                          float* __restrict__ C,
                                                          const int* __restrict__ perm,
                                                          int k, int n) {
    extern __shared__ __align__(16) char smem[];
    float* sC = (float*)smem;
    int* spmM = (int*)(smem + 4 * BUFSZ);
    int* spmN = (int*)(smem + 4 * BUFSZ + 512);
    uint32_t sbase = (uint32_t)__cvta_generic_to_shared(smem);

    int tid = threadIdx.x;
    int wid = tid >> 5, lane = tid & 31;
    int wm = wid >> 2, wn = wid & 3;
    int lr = lane >> 2, lc = lane & 3;

    int t = blockIdx.x;
    int by = (int)((sqrtf(8.0f * (float)t + 1.0f) - 1.0f) * 0.5f);
    while ((by + 1) * (by + 2) / 2 <= t) by++;
    while (by * (by + 1) / 2 > t) by--;
    int bx = t - by * (by + 1) / 2;
    int m0 = by * 128, n0 = bx * 128;

    long prm[4], prn[4];
#pragma unroll
    for (int q = 0; q < 4; q++) {
        int row = (tid + q * 256) >> 3;
        prm[q] = (long)__ldg(&perm[m0 + row]) * n;
        prn[q] = (long)__ldg(&perm[n0 + row]) * n;
    }
    if (tid < 128) {
        spmM[tid] = __ldg(&perm[m0 + tid]);
        spmN[tid] = __ldg(&perm[n0 + tid]);
    }

    float acc[4][4][4];
#pragma unroll
    for (int i = 0; i < 4; i++)
#pragma unroll
        for (int j = 0; j < 4; j++)
#pragma unroll
            for (int q = 0; q < 4; q++) acc[i][j][q] = 0.f;

    int nch = n >> 5;
#pragma unroll
    for (int q = 0; q < 4; q++) {
        int idx = tid + q * 256;
        int row = idx >> 3, c4 = idx & 7;
        CP_ASYNC16(sbase + (row * ASTRIDE + c4 * 4) * 4, &Ap[prm[q] + c4 * 4]);
        CP_ASYNC16(sbase + 2 * BUFSZ + (row * ASTRIDE + c4 * 4) * 4, &Ap[prn[q] + c4 * 4]);
    }
    CP_COMMIT();

    for (int ch = 0; ch < nch; ch++) {
        int b = ch & 1;
        if (ch + 1 < nch) {
            int k0 = (ch + 1) << 5;
            int nb = (ch + 1) & 1;
#pragma unroll
            for (int q = 0; q < 4; q++) {
                int idx = tid + q * 256;
                int row = idx >> 3, c4 = idx & 7;
                CP_ASYNC16(sbase + nb * BUFSZ + (row * ASTRIDE + c4 * 4) * 4,
                           &Ap[prm[q] + k0 + c4 * 4]);
                CP_ASYNC16(sbase + (2 + nb) * BUFSZ + (row * ASTRIDE + c4 * 4) * 4,
                           &Ap[prn[q] + k0 + c4 * 4]);
            }
            CP_COMMIT();
            CP_WAIT(1);
        } else {
            CP_WAIT(0);
        }
        __syncthreads();
        float* sA = (float*)(smem + b * BUFSZ);
        float* sB = (float*)(smem + (2 + b) * BUFSZ);
#pragma unroll
        for (int kt = 0; kt < 4; kt++) {
            int kk = kt * 8;
            uint32_t a[4][4];
#pragma unroll
            for (int i = 0; i < 4; i++) {
                int r0 = wm * 64 + i * 16;
                a[i][0] = __float_as_uint(sA[(r0 + lr) * ASTRIDE + kk + lc]);
                a[i][1] = __float_as_uint(sA[(r0 + lr + 8) * ASTRIDE + kk + lc]);
                a[i][2] = __float_as_uint(sA[(r0 + lr) * ASTRIDE + kk + lc + 4]);
                a[i][3] = __float_as_uint(sA[(r0 + lr + 8) * ASTRIDE + kk + lc + 4]);
            }
#pragma unroll
            for (int j = 0; j < 4; j++) {
                int c0 = wn * 32 + j * 8;
                uint32_t b0 = __float_as_uint(sB[(c0 + lr) * ASTRIDE + kk + lc]);
                uint32_t b1 = __float_as_uint(sB[(c0 + lr) * ASTRIDE + kk + lc + 4]);
#pragma unroll
                for (int i = 0; i < 4; i++) {
                    asm volatile(
                        "mma.sync.aligned.m16n8k8.row.col.f32.tf32.tf32.f32 "
                        "{%0,%1,%2,%3}, {%4,%5,%6,%7}, {%8,%9}, {%0,%1,%2,%3};"
                        : "+f"(acc[i][j][0]), "+f"(acc[i][j][1]),
                          "+f"(acc[i][j][2]), "+f"(acc[i][j][3])
                        : "r"(a[i][0]), "r"(a[i][1]), "r"(a[i][2]), "r"(a[i][3]),
                          "r"(b0), "r"(b1));
                }
            }
        }
        __syncthreads();
    }

#pragma unroll
    for (int i = 0; i < 4; i++) {
#pragma unroll
        for (int j = 0; j < 4; j++) {
            int r0 = wm * 64 + i * 16 + lr;
            int c0 = wn * 32 + j * 8 + 2 * lc;
            sC[r0 * CSTRIDE + c0]           = acc[i][j][0];
            sC[r0 * CSTRIDE + c0 + 1]       = acc[i][j][1];
            sC[(r0 + 8) * CSTRIDE + c0]     = acc[i][j][2];
            sC[(r0 + 8) * CSTRIDE + c0 + 1] = acc[i][j][3];
        }
    }
    __syncthreads();

    for (int e = tid; e < 128 * 128; e += 256) {
        int r = e >> 7, c = e & 127;
        float v = sC[r * CSTRIDE + c] +
                  2.0f * Ap[(size_t)spmM[r] * n + spmN[c]];
        if (m0 + r == n0 + c) v = 0.0f;
        C[(size_t)(m0 + r) * k + n0 + c] = v;
        sC[r * CSTRIDE + c] = v;
    }
    __syncthreads();
    if (bx != by) {
        for (int e = tid; e < 128 * 128; e += 256) {
            int r = e >> 7, c = e & 127;
            C[(size_t)(n0 + r) * k + m0 + c] = sC[c * CSTRIDE + r];
        }
    }
}

__global__ void pool_aug_f32_k(const float* __restrict__ Ap, float* __restrict__ C,
                               const int* __restrict__ perm, int k, int n) {
    __shared__ __align__(16) float As[16][68];
    __shared__ __align__(16) float Bs[16][68];
    __shared__ int sM[64], sN[64];
    int tx = threadIdx.x, ty = threadIdx.y;
    int t = ty * 16 + tx;
    int m0 = blockIdx.y * 64, n0 = blockIdx.x * 64;
    float acc[4][4] = {};

    if (t < 64) {
        sM[t] = __ldg(&perm[m0 + t]);
        sN[t] = __ldg(&perm[n0 + t]);
    }
    __syncthreads();

    for (int k0 = 0; k0 < n; k0 += 16) {
#pragma unroll
        for (int q = 0; q < 4; q++) {
            int idx = t + q * 256;
            int m = idx >> 4, kk = idx & 15;
            As[kk][m] = Ap[(size_t)sM[m] * n + k0 + kk];
            Bs[kk][m] = Ap[(size_t)sN[m] * n + k0 + kk];
        }
        __syncthreads();
#pragma unroll
        for (int kk = 0; kk < 16; kk++) {
            float4 a4 = *(const float4*)&As[kk][ty * 4];
            float4 b4 = *(const float4*)&Bs[kk][tx * 4];
            float a[4] = {a4.x, a4.y, a4.z, a4.w};
            float b[4] = {b4.x, b4.y, b4.z, b4.w};
#pragma unroll
            for (int i = 0; i < 4; i++)
#pragma unroll
                for (int j = 0; j < 4; j++) acc[i][j] += a[i] * b[j];
        }
        __syncthreads();
    }

#pragma unroll
    for (int i = 0; i < 4; i++) {
        int r = m0 + ty * 4 + i;
#pragma unroll
        for (int j = 0; j < 4; j++) {
            int c = n0 + tx * 4 + j;
            float v = acc[i][j] +
                      2.0f * Ap[(size_t)sM[ty * 4 + i] * n + sN[tx * 4 + j]];
            if (r == c) v = 0.0f;
            C[(size_t)r * k + c] = v;
        }
    }
}

// ---------------- simple kernels ----------------

__global__ void rowsum_dinv_k(const float* __restrict__ A, float* __restrict__ dinv, int n) {
    __shared__ float sm[256];
    int row = blockIdx.x;
    float s = 0.f;
    const float* rp = A + (size_t)row * n;
    for (int j = threadIdx.x; j < n; j += 256) s += rp[j];
    sm[threadIdx.x] = s;
    __syncthreads();
    for (int o = 128; o > 0; o >>= 1) {
        if (threadIdx.x < o) sm[threadIdx.x] += sm[threadIdx.x + o];
        __syncthreads();
    }
    if (threadIdx.x == 0) dinv[row] = rsqrtf(sm[0] + 2.0f);
}

__global__ void gemm_n32_k(const float* __restrict__ A, const float* __restrict__ B,
                           float* __restrict__ C, int M, int N, int K) {
    __shared__ __align__(16) float As[32][33];
    __shared__ __align__(16) float Bs[32][32];
    int tid = threadIdx.x;
    int m0 = blockIdx.x * 32;
    int r = tid >> 3, cg = (tid & 7) * 4;
    float acc[4] = {};
    for (int k0 = 0; k0 < K; k0 += 32) {
#pragma unroll
        for (int q = 0; q < 4; q++) {
            int e = tid + q * 256;
            int row = e >> 5, col = e & 31;
            int gr = m0 + row, gk = k0 + col;
            As[row][col] = (gr < M && gk < K) ? A[(size_t)gr * K + gk] : 0.f;
            int bk = k0 + row;
            Bs[row][col] = (bk < K && col < N) ? B[(size_t)bk * N + col] : 0.f;
        }
        __syncthreads();
#pragma unroll
        for (int kk = 0; kk < 32; kk++) {
            float a = As[r][kk];
            float4 b = *(const float4*)&Bs[kk][cg];
            acc[0] += a * b.x; acc[1] += a * b.y; acc[2] += a * b.z; acc[3] += a * b.w;
        }
        __syncthreads();
    }
    int gr = m0 + r;
    if (gr < M) {
#pragma unroll
        for (int j = 0; j < 4; j++) {
            int c = cg + j;
            if (c < N) C[(size_t)gr * N + c] = acc[j];
        }
    }
}

__global__ void scatter_add_k(float* __restrict__ dst, const float* __restrict__ src,
                              const int* __restrict__ perm, int k) {
    int t = blockIdx.x * blockDim.x + threadIdx.x;
    if (t < k * HH) {
        int r = t >> 5, c = t & 31;
        dst[(size_t)perm[r] * HH + c] += src[t];
    }
}

__global__ void logsoftmax_k(const float* __restrict__ X, float* __restrict__ out, int n) {
    int r = blockIdx.x * blockDim.x + threadIdx.x;
    if (r < n) {
        const float* xp = X + (size_t)r * CC;
        float m = -1e30f;
#pragma unroll
        for (int j = 0; j < CC; j++) m = fmaxf(m, xp[j]);
        float s = 0.f;
#pragma unroll
        for (int j = 0; j < CC; j++) s += expf(xp[j] - m);
        float l = logf(s);
        float* op = out + (size_t)r * CC;
#pragma unroll
        for (int j = 0; j < CC; j++) op[j] = xp[j] - m - l;
    }
}

// ---------------- host side ----------------

static void launch_agg(const float* Am, const float* B, float* C,
                       int M, int N, int K, int mode, const float* dinv,
                       const float* bias, int relu, float* part) {
    int Kchunk, S;
    if (K == 2048)      { Kchunk = 128; S = 16; }
    else if (K == 1024) { Kchunk = 64;  S = 16; }
    else if (K == 512)  { Kchunk = 64;  S = 8; }
    else                { Kchunk = 192; S = (K + 191) / 192; }
    dim3 g(M / 256, S);
    agg_gemm_k<<<g, 256, AGG_SMEM>>>(Am, B, part, M, N, K, Kchunk,
                                     mode == 2 ? dinv : nullptr);
    int tot = M * 32;
    agg_reduce_k<<<(tot + 255) / 256, 256>>>(part, C, B, dinv, bias, M, N, S, mode, relu);
}

static void run_gcn_dense(const float* X, const float* A, int n, int Nout,
                          const float* W, const float* b, int relu, float* out,
                          float* pY, float* part, const float* pdinv) {
    gemm_n32_k<<<(n + 31) / 32, 256>>>(X, W, pY, n, Nout, HH);
    launch_agg(A, pY, out, n, Nout, n, 2, pdinv, b, relu, part);
}

static void run_gcn_sparse(const float* X, int Kin, int Nout,
                           const float* W, const float* b, int relu, float* out,
                           float* pY, float* part, const float* dinv0,
                           const int* rowptr, const int* colidx) {
    if (Kin <= 32)
        gemm_n32_k<<<(NN + 31) / 32, 256>>>(X, W, pY, NN, Nout, Kin);
    else
        launch_agg(X, W, pY, NN, Nout, Kin, 0, nullptr, nullptr, 0, part);
    spmm_gcn_k<<<NN / 8, 256>>>(rowptr, colidx, pY, dinv0, b, out, Nout, relu);
}

extern "C" void kernel_launch(void* const* d_in, const int* in_sizes, int n_in,
                              void* d_out, int out_size) {
    const float* x   = (const float*)d_in[0];
    const int*   ei  = (const int*)d_in[1];
    const float* Wi  = (const float*)d_in[2];
    const float* bi  = (const float*)d_in[3];
    const float* dW  = (const float*)d_in[4];
    const float* db  = (const float*)d_in[5];
    const float* pp  = (const float*)d_in[6];
    const float* uW  = (const float*)d_in[7];
    const float* ub  = (const float*)d_in[8];
    const float* Wf  = (const float*)d_in[9];
    const float* bf  = (const float*)d_in[10];
    float* out = (float*)d_out;

    cudaFuncSetAttribute(pool_aug_s8_k, cudaFuncAttributeMaxDynamicSharedMemorySize, AUG_SMEM);
    cudaFuncSetAttribute(pool_aug_tf32_k, cudaFuncAttributeMaxDynamicSharedMemorySize, AUG_SMEM);
    cudaFuncSetAttribute(agg_gemm_k, cudaFuncAttributeMaxDynamicSharedMemorySize, AGG_SMEM);

    float *pA1, *pA2, *pA3, *ppart;
    int8_t* pA8;
    float *px0, *pxs0, *pxs1, *pxs2, *phA, *phB, *pY, *pdinv;
    int *pperm, *prowptr, *pcolidx, *pdeg;
    cudaGetSymbolAddress((void**)&pA8, g_A8);
    cudaGetSymbolAddress((void**)&pA1, g_A1);
    cudaGetSymbolAddress((void**)&pA2, g_A2);
    cudaGetSymbolAddress((void**)&pA3, g_A3);
    cudaGetSymbolAddress((void**)&ppart, g_part);
    cudaGetSymbolAddress((void**)&prowptr, g_rowptr);
    cudaGetSymbolAddress((void**)&pcolidx, g_colidx);
    cudaGetSymbolAddress((void**)&pdeg, g_deg);
    cudaGetSymbolAddress((void**)&px0, g_x0);
    cudaGetSymbolAddress((void**)&pxs0, g_xs0);
    cudaGetSymbolAddress((void**)&pxs1, g_xs1);
    cudaGetSymbolAddress((void**)&pxs2, g_xs2);
    cudaGetSymbolAddress((void**)&phA, g_hA);
    cudaGetSymbolAddress((void**)&phB, g_hB);
    cudaGetSymbolAddress((void**)&pY, g_Y);
    cudaGetSymbolAddress((void**)&pdinv, g_dinv);
    cudaGetSymbolAddress((void**)&pperm, g_perm);

    int* pp0 = pperm;
    int* pp1 = pperm + 2048;
    int* pp2 = pperm + 3072;
    float* dinv0 = pdinv;
    float* dinv1 = pdinv + 4096;
    float* dinv2 = pdinv + 6144;
    float* dinv3 = pdinv + 7168;

    // ---- build adjacency + CSR + dinv0 ----
    cudaMemsetAsync(pA8, 0, (size_t)NN * NN);
    scatter_edges_k<<<(EE + 255) / 256, 256>>>(ei, pA8);
    degree_dinv_k<<<NN / 8, 256>>>(pA8, pdeg, dinv0);
    prefix_k<<<1, 1024>>>(pdeg, prowptr);
    csr_fill_k<<<NN / 8, 256>>>(pA8, prowptr, pcolidx);

    // ---- x = relu(gcn(x, A, Wi, bi)); h = relu(gcn(x, A, dW0, db0)) ----
    run_gcn_sparse(x, FF, HH, Wi, bi, 1, px0, pY, ppart, dinv0, prowptr, pcolidx);
    run_gcn_sparse(px0, HH, HH, dW, db, 1, pxs0, pY, ppart, dinv0, prowptr, pcolidx);

    // ================= down path =================
    // i = 1 (4096 -> 2048): fused score/sort/gather + perm-indirect s8 pooled augment
    score_sort_gather_k<<<1, 1024>>>(pxs0, pp + 0, NN, 2048, pp0, phA);
    {
        int nt = 2048 / 128;
        pool_aug_s8_k<<<nt * (nt + 1) / 2, 256, AUG_SMEM>>>(pA8, pA1, pp0, 2048, NN);
    }
    rowsum_dinv_k<<<2048, 256>>>(pA1, dinv1, 2048);
    run_gcn_dense(phA, pA1, 2048, HH, dW + 1024, db + 32, 1, pxs1, pY, ppart, dinv1);

    // i = 2 (2048 -> 1024): tf32 pooled augment
    score_sort_gather_k<<<1, 1024>>>(pxs1, pp + 32, 2048, 1024, pp1, phA);
    {
        int nt = 1024 / 128;
        pool_aug_tf32_k<<<nt * (nt + 1) / 2, 256, AUG_SMEM>>>(pA1, pA2, pp1, 1024, 2048);
    }
    rowsum_dinv_k<<<1024, 256>>>(pA2, dinv2, 1024);
    run_gcn_dense(phA, pA2, 1024, HH, dW + 2048, db + 64, 1, pxs2, pY, ppart, dinv2);

    // i = 3 (1024 -> 512): fp32 pooled augment
    score_sort_gather_k<<<1, 1024>>>(pxs2, pp + 64, 1024, 512, pp2, phA);
    pool_aug_f32_k<<<dim3(512 / 64, 512 / 64), dim3(16, 16)>>>(pA2, pA3, pp2, 512, 1024);
    rowsum_dinv_k<<<512, 256>>>(pA3, dinv3, 512);
    run_gcn_dense(phA, pA3, 512, HH, dW + 3072, db + 96, 1, phB, pY, ppart, dinv3);

    // ================= up path =================
    cudaMemcpyAsync(phA, pxs2, (size_t)1024 * HH * sizeof(float), cudaMemcpyDeviceToDevice);
    scatter_add_k<<<(512 * HH + 255) / 256, 256>>>(phA, phB, pp2, 512);
    run_gcn_dense(phA, pA2, 1024, HH, uW, ub, 1, phB, pY, ppart, dinv2);

    cudaMemcpyAsync(phA, pxs1, (size_t)2048 * HH * sizeof(float), cudaMemcpyDeviceToDevice);
    scatter_add_k<<<(1024 * HH + 255) / 256, 256>>>(phA, phB, pp1, 1024);
    run_gcn_dense(phA, pA1, 2048, HH, uW + 1024, ub + 32, 1, phB, pY, ppart, dinv1);

    cudaMemcpyAsync(phA, pxs0, (size_t)NN * HH * sizeof(float), cudaMemcpyDeviceToDevice);
    scatter_add_k<<<(2048 * HH + 255) / 256, 256>>>(phA, phB, pp0, 2048);
    run_gcn_sparse(phA, HH, HH, uW + 2048, ub + 64, 1, phB, pY, ppart, dinv0, prowptr, pcolidx);

    // ---- final gcn + log_softmax ----
    run_gcn_sparse(phB, HH, CC, Wf, bf, 0, phA, pY, ppart, dinv0, prowptr, pcolidx);
    logsoftmax_k<<<(NN + 255) / 256, 256>>>(phA, out, NN);
}

// round 14
// speedup vs baseline: 1.3196x; 1.3196x over previous
#include <cuda_runtime.h>
#include <cuda_bf16.h>
#include <math.h>
#include <stdint.h>

#define NN 4096
#define FF 1433
#define HH 32
#define CC 7
#define EE 131072

// ---------------- device scratch ----------------
__device__ int8_t g_A8[(size_t)NN * NN];
__device__ float g_G[(size_t)NN * NN / 2];
__device__ float g_A1[(size_t)2048 * 2048];
__device__ float g_A2[(size_t)1024 * 1024];
__device__ float g_A3[(size_t)512 * 512];
__device__ float g_part[(size_t)32 * 4096 * 32];
__device__ int   g_rowptr[NN + 1];
__device__ int   g_colidx[2 * EE];
__device__ int   g_deg[NN];
__device__ float g_x0[NN * HH];
__device__ float g_xs0[NN * HH];
__device__ float g_xs1[2048 * HH];
__device__ float g_xs2[1024 * HH];
__device__ float g_hA[NN * HH];
__device__ float g_hB[NN * HH];
__device__ float g_Y[NN * HH];
__device__ float g_dinv[8192];
__device__ float g_score[NN];
__device__ int   g_perm[NN];

#define S8STRIDE 144
#define ASTRIDE 36
#define CSTRIDE 129
#define BUFSZ 18432
#define AUG_SMEM (4 * BUFSZ + 512)

#define CP_ASYNC16(dst, src) \
    asm volatile("cp.async.cg.shared.global [%0], [%1], 16;" :: "r"(dst), "l"(src))
#define CP_COMMIT() asm volatile("cp.async.commit_group;" ::: "memory")
#define CP_WAIT(n)  asm volatile("cp.async.wait_group %0;" :: "n"(n) : "memory")

// ---------------- level-0 sparse path ----------------

__global__ void scatter_edges_k(const int* __restrict__ ei, int8_t* __restrict__ A8) {
    int e = blockIdx.x * blockDim.x + threadIdx.x;
    if (e < EE) {
        int u = ei[e], v = ei[EE + e];
        if (u != v) {
            A8[(size_t)u * NN + v] = 1;
            A8[(size_t)v * NN + u] = 1;
        }
    }
}

__global__ void degree_dinv_k(const int8_t* __restrict__ A8, int* __restrict__ deg,
                              float* __restrict__ dinv) {
    int warp = (blockIdx.x * blockDim.x + threadIdx.x) >> 5;
    int lane = threadIdx.x & 31;
    if (warp >= NN) return;
    const uchar4* row = (const uchar4*)&A8[(size_t)warp * NN];
    int cnt = 0;
    for (int it = lane; it < NN / 4; it += 32) {
        uchar4 v = row[it];
        cnt += (v.x != 0) + (v.y != 0) + (v.z != 0) + (v.w != 0);
    }
#pragma unroll
    for (int o = 16; o > 0; o >>= 1) cnt += __shfl_down_sync(0xffffffffu, cnt, o);
    if (lane == 0) {
        deg[warp] = cnt;
        dinv[warp] = rsqrtf((float)cnt + 2.0f);
    }
}

__global__ void prefix_k(const int* __restrict__ deg, int* __restrict__ rowptr) {
    __shared__ int part[1024];
    int tid = threadIdx.x;
    int base = tid * 4;
    int d0 = deg[base], d1 = deg[base + 1], d2 = deg[base + 2], d3 = deg[base + 3];
    int s = d0 + d1 + d2 + d3;
    part[tid] = s;
    __syncthreads();
    for (int o = 1; o < 1024; o <<= 1) {
        int v = (tid >= o) ? part[tid - o] : 0;
        __syncthreads();
        part[tid] += v;
        __syncthreads();
    }
    int excl = (tid == 0) ? 0 : part[tid - 1];
    rowptr[base]     = excl;
    rowptr[base + 1] = excl + d0;
    rowptr[base + 2] = excl + d0 + d1;
    rowptr[base + 3] = excl + d0 + d1 + d2;
    if (tid == 1023) rowptr[4096] = part[1023];
}

__global__ void csr_fill_k(const int8_t* __restrict__ A8, const int* __restrict__ rowptr,
                           int* __restrict__ colidx) {
    int warp = (blockIdx.x * blockDim.x + threadIdx.x) >> 5;
    int lane = threadIdx.x & 31;
    if (warp >= NN) return;
    const int8_t* row = &A8[(size_t)warp * NN];
    int pos = rowptr[warp];
    for (int c0 = 0; c0 < NN; c0 += 128) {
        uint32_t w = *(const uint32_t*)&row[c0 + lane * 4];
        int b0 = (w & 0xffu) != 0, b1 = (w & 0xff00u) != 0;
        int b2 = (w & 0xff0000u) != 0, b3 = (w & 0xff000000u) != 0;
        int cnt = b0 + b1 + b2 + b3;
        int inc = cnt;
#pragma unroll
        for (int o = 1; o < 32; o <<= 1) {
            int v = __shfl_up_sync(0xffffffffu, inc, o);
            if (lane >= o) inc += v;
        }
        int excl = inc - cnt;
        int total = __shfl_sync(0xffffffffu, inc, 31);
        int wr = pos + excl;
        int cb = c0 + lane * 4;
        if (b0) colidx[wr++] = cb;
        if (b1) colidx[wr++] = cb + 1;
        if (b2) colidx[wr++] = cb + 2;
        if (b3) colidx[wr++] = cb + 3;
        pos += total;
    }
}

__global__ void spmm_gcn_k(const int* __restrict__ rowptr, const int* __restrict__ colidx,
                           const float* __restrict__ Y, const float* __restrict__ dinv,
                           const float* __restrict__ bias, float* __restrict__ out,
                           int N, int relu) {
    int warp = (blockIdx.x * blockDim.x + threadIdx.x) >> 5;
    int lane = threadIdx.x & 31;
    if (warp >= NN) return;
    int s = rowptr[warp], e = rowptr[warp + 1];
    float acc = 0.f;
    bool act = lane < N;
    for (int base = s; base < e; base += 32) {
        int idx = (base + lane < e) ? colidx[base + lane] : 0;
        int cnt = min(32, e - base);
        int t = 0;
        for (; t + 8 <= cnt; t += 8) {
            float v[8];
#pragma unroll
            for (int q = 0; q < 8; q++) {
                int j = __shfl_sync(0xffffffffu, idx, t + q);
                v[q] = act ? dinv[j] * Y[(size_t)j * N + lane] : 0.f;
            }
#pragma unroll
            for (int q = 0; q < 8; q++) acc += v[q];
        }
        for (; t < cnt; t++) {
            int j = __shfl_sync(0xffffffffu, idx, t);
            if (act) acc += dinv[j] * Y[(size_t)j * N + lane];
        }
    }
    if (act) {
        float dr = dinv[warp];
        float v = dr * (acc + 2.0f * dr * Y[(size_t)warp * N + lane]) + bias[lane];
        if (relu) v = fmaxf(v, 0.0f);
        out[(size_t)warp * N + lane] = v;
    }
}

// ---------------- split-K aggregate GEMM ----------------
#define SAOFF (192 * 32)
#define AGG_SMEM ((192 * 32 + 256 * 33) * 4)

__global__ void __launch_bounds__(256) agg_gemm_k(
    const float* __restrict__ A, const float* __restrict__ B,
    float* __restrict__ part, int M, int N, int K, int Kchunk,
    const float* __restrict__ dinv)
{
    extern __shared__ float sm[];
    float* sB = sm;
    float* sA = sm + SAOFF;

    int tid = threadIdx.x;
    int warp = tid >> 5, lane = tid & 31;
    int myrow = warp * 32 + lane;
    int m0 = blockIdx.x * 256;
    int kc = blockIdx.y * Kchunk;
    bool K4 = (K & 3) == 0;

    for (int i = tid; i < Kchunk * 32; i += 256) {
        int k = i >> 5, c = i & 31;
        int gk = kc + k;
        float bv = 0.f;
        if (gk < K && c < N) {
            bv = B[(size_t)gk * N + c];
            if (dinv) bv *= dinv[gk];
        }
        sB[k * 32 + c] = bv;
    }

    float acc[32];
#pragma unroll
    for (int i = 0; i < 32; i++) acc[i] = 0.f;

    int ksteps = Kchunk >> 5;
    float pv[32];

#define LOADPV(KS) do { \
        int _ks = (KS); \
        _Pragma("unroll") \
        for (int q = 0; q < 8; q++) { \
            int idx = tid + q * 256; \
            int row = idx >> 3, c4 = idx & 7; \
            int gk = kc + _ks * 32 + c4 * 4; \
            const float* ap = &A[(size_t)(m0 + row) * K + gk]; \
            if (K4) { \
                float4 v = (gk < K) ? *(const float4*)ap : make_float4(0, 0, 0, 0); \
                pv[q * 4 + 0] = v.x; pv[q * 4 + 1] = v.y; \
                pv[q * 4 + 2] = v.z; pv[q * 4 + 3] = v.w; \
            } else { \
                _Pragma("unroll") \
                for (int i = 0; i < 4; i++) \
                    pv[q * 4 + i] = (gk + i < K) ? ap[i] : 0.f; \
            } \
        } \
    } while (0)

    LOADPV(0);

    for (int ks = 0; ks < ksteps; ks++) {
        __syncthreads();
#pragma unroll
        for (int q = 0; q < 8; q++) {
            int idx = tid + q * 256;
            int row = idx >> 3, c4 = idx & 7;
#pragma unroll
            for (int i = 0; i < 4; i++)
                sA[row * 33 + c4 * 4 + i] = pv[q * 4 + i];
        }
        __syncthreads();
        if (ks + 1 < ksteps) LOADPV(ks + 1);
#pragma unroll
        for (int kk = 0; kk < 32; kk++) {
            float a = sA[myrow * 33 + kk];
            const float4* bp = (const float4*)&sB[(ks * 32 + kk) * 32];
#pragma unroll
            for (int c4 = 0; c4 < 8; c4++) {
                float4 b = bp[c4];
                acc[c4 * 4 + 0] += a * b.x;
                acc[c4 * 4 + 1] += a * b.y;
                acc[c4 * 4 + 2] += a * b.z;
                acc[c4 * 4 + 3] += a * b.w;
            }
        }
    }

    float* pp = &part[(size_t)blockIdx.y * M * 32 + (size_t)(m0 + myrow) * 32];
#pragma unroll
    for (int c4 = 0; c4 < 8; c4++) {
        float4 v = make_float4(acc[c4 * 4], acc[c4 * 4 + 1], acc[c4 * 4 + 2], acc[c4 * 4 + 3]);
        *(float4*)&pp[c4 * 4] = v;
    }
}

__global__ void agg_reduce_k(const float* __restrict__ part, float* __restrict__ C,
                             const float* __restrict__ Y, const float* __restrict__ dinv,
                             const float* __restrict__ bias, int M, int N, int S,
                             int mode, int relu) {
    int t = blockIdx.x * blockDim.x + threadIdx.x;
    if (t >= M * 32) return;
    int r = t >> 5, c = t & 31;
    float s = 0.f;
    for (int i = 0; i < S; i++) s += part[(size_t)i * M * 32 + t];
    if (c < N) {
        float v = s;
        if (mode == 2) {
            float dr = dinv[r];
            v = dr * (v + 2.0f * dr * Y[(size_t)r * N + c]) + bias[c];
        }
        if (relu) v = fmaxf(v, 0.0f);
        C[(size_t)r * N + c] = v;
    }
}

// ---------------- fused pool+augment (cp.async pipelined, compact G) ----------------

__global__ void __launch_bounds__(256, 2) pool_aug_s8_k(const int8_t* __restrict__ G,
                                                        float* __restrict__ C,
                                                        const int* __restrict__ perm,
                                                        int k, int n) {
    extern __shared__ __align__(16) char smem[];
    float* sC = (float*)smem;
    int* spm = (int*)(smem + 4 * BUFSZ);
    uint32_t sbase = (uint32_t)__cvta_generic_to_shared(smem);

    int tid = threadIdx.x;
    int wid = tid >> 5, lane = tid & 31;
    int wm = wid >> 2, wn = wid & 3;
    int lr = lane >> 2, lc = lane & 3;

    int t = blockIdx.x;
    int by = (int)((sqrtf(8.0f * (float)t + 1.0f) - 1.0f) * 0.5f);
    while ((by + 1) * (by + 2) / 2 <= t) by++;
    while (by * (by + 1) / 2 > t) by--;
    int bx = t - by * (by + 1) / 2;
    int m0 = by * 128, n0 = bx * 128;

    int acc[4][4][4];
#pragma unroll
    for (int i = 0; i < 4; i++)
#pragma unroll
        for (int j = 0; j < 4; j++)
#pragma unroll
            for (int q = 0; q < 4; q++) acc[i][j][q] = 0;

    int nch = n >> 7;
#pragma unroll
    for (int q = 0; q < 4; q++) {
        int idx = tid + q * 256;
        int row = idx >> 3, s = idx & 7;
        CP_ASYNC16(sbase + row * S8STRIDE + s * 16,
                   &G[(size_t)(m0 + row) * n + s * 16]);
        CP_ASYNC16(sbase + 2 * BUFSZ + row * S8STRIDE + s * 16,
                   &G[(size_t)(n0 + row) * n + s * 16]);
    }
    CP_COMMIT();

    for (int ch = 0; ch < nch; ch++) {
        int b = ch & 1;
        if (ch + 1 < nch) {
            int k0 = (ch + 1) << 7;
            int nb = (ch + 1) & 1;
#pragma unroll
            for (int q = 0; q < 4; q++) {
                int idx = tid + q * 256;
                int row = idx >> 3, s = idx & 7;
                CP_ASYNC16(sbase + nb * BUFSZ + row * S8STRIDE + s * 16,
                           &G[(size_t)(m0 + row) * n + k0 + s * 16]);
                CP_ASYNC16(sbase + (2 + nb) * BUFSZ + row * S8STRIDE + s * 16,
                           &G[(size_t)(n0 + row) * n + k0 + s * 16]);
            }
            CP_COMMIT();
            CP_WAIT(1);
        } else {
            CP_WAIT(0);
        }
        __syncthreads();
        int8_t* sA = (int8_t*)smem + b * BUFSZ;
        int8_t* sB = (int8_t*)smem + (2 + b) * BUFSZ;
#pragma unroll
        for (int kt = 0; kt < 4; kt++) {
            int kk = kt * 32;
            uint32_t a[4][4];
#pragma unroll
            for (int i = 0; i < 4; i++) {
                int r0 = wm * 64 + i * 16;
                a[i][0] = *(const uint32_t*)&sA[(r0 + lr) * S8STRIDE + kk + lc * 4];
                a[i][1] = *(const uint32_t*)&sA[(r0 + lr + 8) * S8STRIDE + kk + lc * 4];
                a[i][2] = *(const uint32_t*)&sA[(r0 + lr) * S8STRIDE + kk + lc * 4 + 16];
                a[i][3] = *(const uint32_t*)&sA[(r0 + lr + 8) * S8STRIDE + kk + lc * 4 + 16];
            }
#pragma unroll
            for (int j = 0; j < 4; j++) {
                int c0 = wn * 32 + j * 8;
                uint32_t b0 = *(const uint32_t*)&sB[(c0 + lr) * S8STRIDE + kk + lc * 4];
                uint32_t b1 = *(const uint32_t*)&sB[(c0 + lr) * S8STRIDE + kk + lc * 4 + 16];
#pragma unroll
                for (int i = 0; i < 4; i++) {
                    asm volatile(
                        "mma.sync.aligned.m16n8k32.row.col.s32.s8.s8.s32 "
                        "{%0,%1,%2,%3}, {%4,%5,%6,%7}, {%8,%9}, {%0,%1,%2,%3};"
                        : "+r"(acc[i][j][0]), "+r"(acc[i][j][1]),
                          "+r"(acc[i][j][2]), "+r"(acc[i][j][3])
                        : "r"(a[i][0]), "r"(a[i][1]), "r"(a[i][2]), "r"(a[i][3]),
                          "r"(b0), "r"(b1));
                }
            }
        }
        __syncthreads();
    }

    if (tid < 128) spm[tid] = perm[n0 + tid];
#pragma unroll
    for (int i = 0; i < 4; i++) {
#pragma unroll
        for (int j = 0; j < 4; j++) {
            int r0 = wm * 64 + i * 16 + lr;
            int c0 = wn * 32 + j * 8 + 2 * lc;
            sC[r0 * CSTRIDE + c0]           = (float)acc[i][j][0];
            sC[r0 * CSTRIDE + c0 + 1]       = (float)acc[i][j][1];
            sC[(r0 + 8) * CSTRIDE + c0]     = (float)acc[i][j][2];
            sC[(r0 + 8) * CSTRIDE + c0 + 1] = (float)acc[i][j][3];
        }
    }
    __syncthreads();

    for (int e = tid; e < 128 * 128; e += 256) {
        int r = e >> 7, c = e & 127;
        float v = sC[r * CSTRIDE + c] + 2.0f * (float)G[(size_t)(m0 + r) * n + spm[c]];
        if (m0 + r == n0 + c) v = 0.0f;
        C[(size_t)(m0 + r) * k + n0 + c] = v;
        sC[r * CSTRIDE + c] = v;
    }
    __syncthreads();
    if (bx != by) {
        for (int e = tid; e < 128 * 128; e += 256) {
            int r = e >> 7, c = e & 127;
            C[(size_t)(n0 + r) * k + m0 + c] = sC[c * CSTRIDE + r];
        }
    }
}

__global__ void __launch_bounds__(256, 2) pool_aug_tf32_k(const float* __restrict__ G,
                                                          float* __restrict__ C,
                                                          const int* __restrict__ perm,
                                                          int k, int n) {
    extern __shared__ __align__(16) char smem[];
    float* sC = (float*)smem;
    int* spm = (int*)(smem + 4 * BUFSZ);
    uint32_t sbase = (uint32_t)__cvta_generic_to_shared(smem);

    int tid = threadIdx.x;
    int wid = tid >> 5, lane = tid & 31;
    int wm = wid >> 2, wn = wid & 3;
    int lr = lane >> 2, lc = lane & 3;

    int t = blockIdx.x;
    int by = (int)((sqrtf(8.0f * (float)t + 1.0f) - 1.0f) * 0.5f);
    while ((by + 1) * (by + 2) / 2 <= t) by++;
    while (by * (by + 1) / 2 > t) by--;
    int bx = t - by * (by + 1) / 2;
    int m0 = by * 128, n0 = bx * 128;

    float acc[4][4][4];
#pragma unroll
    for (int i = 0; i < 4; i++)
#pragma unroll
        for (int j = 0; j < 4; j++)
#pragma unroll
            for (int q = 0; q < 4; q++) acc[i][j][q] = 0.f;

    int nch = n >> 5;
#pragma unroll
    for (int q = 0; q < 4; q++) {
        int idx = tid + q * 256;
        int row = idx >> 3, c4 = idx & 7;
        CP_ASYNC16(sbase + (row * ASTRIDE + c4 * 4) * 4,
                   &G[(size_t)(m0 + row) * n + c4 * 4]);
        CP_ASYNC16(sbase + 2 * BUFSZ + (row * ASTRIDE + c4 * 4) * 4,
                   &G[(size_t)(n0 + row) * n + c4 * 4]);
    }
    CP_COMMIT();

    for (int ch = 0; ch < nch; ch++) {
        int b = ch & 1;
        if (ch + 1 < nch) {
            int k0 = (ch + 1) << 5;
            int nb = (ch + 1) & 1;
#pragma unroll
            for (int q = 0; q < 4; q++) {
                int idx = tid + q * 256;
                int row = idx >> 3, c4 = idx & 7;
                CP_ASYNC16(sbase + nb * BUFSZ + (row * ASTRIDE + c4 * 4) * 4,
                           &G[(size_t)(m0 + row) * n + k0 + c4 * 4]);
                CP_ASYNC16(sbase + (2 + nb) * BUFSZ + (row * ASTRIDE + c4 * 4) * 4,
                           &G[(size_t)(n0 + row) * n + k0 + c4 * 4]);
            }
            CP_COMMIT();
            CP_WAIT(1);
        } else {
            CP_WAIT(0);
        }
        __syncthreads();
        float* sA = (float*)(smem + b * BUFSZ);
        float* sB = (float*)(smem + (2 + b) * BUFSZ);
#pragma unroll
        for (int kt = 0; kt < 4; kt++) {
            int kk = kt * 8;
            uint32_t a[4][4];
#pragma unroll
            for (int i = 0; i < 4; i++) {
                int r0 = wm * 64 + i * 16;
                a[i][0] = __float_as_uint(sA[(r0 + lr) * ASTRIDE + kk + lc]);
                a[i][1] = __float_as_uint(sA[(r0 + lr + 8) * ASTRIDE + kk + lc]);
                a[i][2] = __float_as_uint(sA[(r0 + lr) * ASTRIDE + kk + lc + 4]);
                a[i][3] = __float_as_uint(sA[(r0 + lr + 8) * ASTRIDE + kk + lc + 4]);
            }
#pragma unroll
            for (int j = 0; j < 4; j++) {
                int c0 = wn * 32 + j * 8;
                uint32_t b0 = __float_as_uint(sB[(c0 + lr) * ASTRIDE + kk + lc]);
                uint32_t b1 = __float_as_uint(sB[(c0 + lr) * ASTRIDE + kk + lc + 4]);
#pragma unroll
                for (int i = 0; i < 4; i++) {
                    asm volatile(
                        "mma.sync.aligned.m16n8k8.row.col.f32.tf32.tf32.f32 "
                        "{%0,%1,%2,%3}, {%4,%5,%6,%7}, {%8,%9}, {%0,%1,%2,%3};"
                        : "+f"(acc[i][j][0]), "+f"(acc[i][j][1]),
                          "+f"(acc[i][j][2]), "+f"(acc[i][j][3])
                        : "r"(a[i][0]), "r"(a[i][1]), "r"(a[i][2]), "r"(a[i][3]),
                          "r"(b0), "r"(b1));
                }
            }
        }
        __syncthreads();
    }

    if (tid < 128) spm[tid] = perm[n0 + tid];
#pragma unroll
    for (int i = 0; i < 4; i++) {
#pragma unroll
        for (int j = 0; j < 4; j++) {
            int r0 = wm * 64 + i * 16 + lr;
            int c0 = wn * 32 + j * 8 + 2 * lc;
            sC[r0 * CSTRIDE + c0]           = acc[i][j][0];
            sC[r0 * CSTRIDE + c0 + 1]       = acc[i][j][1];
            sC[(r0 + 8) * CSTRIDE + c0]     = acc[i][j][2];
            sC[(r0 + 8) * CSTRIDE + c0 + 1] = acc[i][j][3];
        }
    }
    __syncthreads();

    for (int e = tid; e < 128 * 128; e += 256) {
        int r = e >> 7, c = e & 127;
        float v = sC[r * CSTRIDE + c] + 2.0f * G[(size_t)(m0 + r) * n + spm[c]];
        if (m0 + r == n0 + c) v = 0.0f;
        C[(size_t)(m0 + r) * k + n0 + c] = v;
        sC[r * CSTRIDE + c] = v;
    }
    __syncthreads();
    if (bx != by) {
        for (int e = tid; e < 128 * 128; e += 256) {
            int r = e >> 7, c = e & 127;
            C[(size_t)(n0 + r) * k + m0 + c] = sC[c * CSTRIDE + r];
        }
    }
}

__global__ void pool_aug_f32_k(const float* __restrict__ G, float* __restrict__ C,
                               const int* __restrict__ perm, int k, int n) {
    __shared__ __align__(16) float As[16][68];
    __shared__ __align__(16) float Bs[16][68];
    __shared__ int spm[64];
    int tx = threadIdx.x, ty = threadIdx.y;
    int t = ty * 16 + tx;
    int m0 = blockIdx.y * 64, n0 = blockIdx.x * 64;
    float acc[4][4] = {};

    if (t < 64) spm[t] = perm[n0 + t];

    for (int k0 = 0; k0 < n; k0 += 16) {
#pragma unroll
        for (int q = 0; q < 4; q++) {
            int idx = t + q * 256;
            int m = idx >> 4, kk = idx & 15;
            As[kk][m] = G[(size_t)(m0 + m) * n + k0 + kk];
            Bs[kk][m] = G[(size_t)(n0 + m) * n + k0 + kk];
        }
        __syncthreads();
#pragma unroll
        for (int kk = 0; kk < 16; kk++) {
            float4 a4 = *(const float4*)&As[kk][ty * 4];
            float4 b4 = *(const float4*)&Bs[kk][tx * 4];
            float a[4] = {a4.x, a4.y, a4.z, a4.w};
            float b[4] = {b4.x, b4.y, b4.z, b4.w};
#pragma unroll
            for (int i = 0; i < 4; i++)
#pragma unroll
                for (int j = 0; j < 4; j++) acc[i][j] += a[i] * b[j];
        }
        __syncthreads();
    }

#pragma unroll
    for (int i = 0; i < 4; i++) {
        int r = m0 + ty * 4 + i;
#pragma unroll
        for (int j = 0; j < 4; j++) {
            int c = n0 + tx * 4 + j;
            float v = acc[i][j] + 2.0f * G[(size_t)r * n + spm[tx * 4 + j]];
            if (r == c) v = 0.0f;
            C[(size_t)r * k + c] = v;
        }
    }
}

// ---------------- simple kernels ----------------

__global__ void rowsum_dinv_k(const float* __restrict__ A, float* __restrict__ dinv, int n) {
    __shared__ float sm[256];
    int row = blockIdx.x;
    float s = 0.f;
    const float* rp = A + (size_t)row * n;
    for (int j = threadIdx.x; j < n; j += 256) s += rp[j];
    sm[threadIdx.x] = s;
    __syncthreads();
    for (int o = 128; o > 0; o >>= 1) {
        if (threadIdx.x < o) sm[threadIdx.x] += sm[threadIdx.x + o];
        __syncthreads();
    }
    if (threadIdx.x == 0) dinv[row] = rsqrtf(sm[0] + 2.0f);
}

__global__ void gather_rows_s8_k(const int8_t* __restrict__ A8, const int* __restrict__ perm,
                                 int8_t* __restrict__ G, int n) {
    int row = blockIdx.x;
    int p = perm[row];
    const int4* src = (const int4*)&A8[(size_t)p * n];
    int4* dst = (int4*)&G[(size_t)row * n];
    for (int i = threadIdx.x; i < n / 16; i += 256) dst[i] = src[i];
}

__global__ void gather_rows_f32_k(const float* __restrict__ A, const int* __restrict__ perm,
                                  float* __restrict__ G, int n) {
    int row = blockIdx.x;
    int p = perm[row];
    const float4* src = (const float4*)&A[(size_t)p * n];
    float4* dst = (float4*)&G[(size_t)row * n];
    for (int i = threadIdx.x; i < n / 4; i += 256) dst[i] = src[i];
}

__global__ void gemm_n32_k(const float* __restrict__ A, const float* __restrict__ B,
                           float* __restrict__ C, int M, int N, int K) {
    __shared__ __align__(16) float As[32][33];
    __shared__ __align__(16) float Bs[32][32];
    int tid = threadIdx.x;
    int m0 = blockIdx.x * 32;
    int r = tid >> 3, cg = (tid & 7) * 4;
    float acc[4] = {};
    for (int k0 = 0; k0 < K; k0 += 32) {
#pragma unroll
        for (int q = 0; q < 4; q++) {
            int e = tid + q * 256;
            int row = e >> 5, col = e & 31;
            int gr = m0 + row, gk = k0 + col;
            As[row][col] = (gr < M && gk < K) ? A[(size_t)gr * K + gk] : 0.f;
            int bk = k0 + row;
            Bs[row][col] = (bk < K && col < N) ? B[(size_t)bk * N + col] : 0.f;
        }
        __syncthreads();
#pragma unroll
        for (int kk = 0; kk < 32; kk++) {
            float a = As[r][kk];
            float4 b = *(const float4*)&Bs[kk][cg];
            acc[0] += a * b.x; acc[1] += a * b.y; acc[2] += a * b.z; acc[3] += a * b.w;
        }
        __syncthreads();
    }
    int gr = m0 + r;
    if (gr < M) {
#pragma unroll
        for (int j = 0; j < 4; j++) {
            int c = cg + j;
            if (c < N) C[(size_t)gr * N + c] = acc[j];
        }
    }
}

__global__ void score_k(const float* __restrict__ h, const float* __restrict__ p,
                        float* __restrict__ score, int n) {
    __shared__ float ps[HH];
    __shared__ float pn;
    if (threadIdx.x < HH) ps[threadIdx.x] = p[threadIdx.x];
    __syncthreads();
    if (threadIdx.x == 0) {
        float s = 0.f;
        for (int i = 0; i < HH; i++) s += ps[i] * ps[i];
        pn = sqrtf(s);
    }
    __syncthreads();
    int i = blockIdx.x * blockDim.x + threadIdx.x;
    if (i < n) {
        float s = 0.f;
        const float* hp = h + (size_t)i * HH;
#pragma unroll
        for (int c = 0; c < HH; c++) s += hp[c] * ps[c];
        score[i] = tanhf(s / pn);
    }
}

__global__ void sort_topk_k(const float* __restrict__ score, int n,
                            int* __restrict__ perm, int k) {
    __shared__ unsigned long long sk[4096];
    int tid = threadIdx.x;
    for (int i = tid; i < n; i += 1024) {
        unsigned u = __float_as_uint(score[i]);
        u = (u & 0x80000000u) ? ~u : (u | 0x80000000u);
        sk[i] = ((unsigned long long)(~u) << 32) | (unsigned)i;
    }
    __syncthreads();
    for (int kk = 2; kk <= n; kk <<= 1) {
        for (int j = kk >> 1; j > 0; j >>= 1) {
            for (int idx = tid; idx < n; idx += 1024) {
                int ixj = idx ^ j;
                if (ixj > idx) {
                    bool up = ((idx & kk) == 0);
                    unsigned long long a = sk[idx], b = sk[ixj];
                    if ((a > b) == up) { sk[idx] = b; sk[ixj] = a; }
                }
            }
            __syncthreads();
        }
    }
    for (int r = tid; r < k; r += 1024) perm[r] = (int)(sk[r] & 0xffffffffULL);
}

__global__ void gather_h_k(const float* __restrict__ h, const int* __restrict__ perm,
                           const float* __restrict__ score, float* __restrict__ out, int k) {
    int t = blockIdx.x * blockDim.x + threadIdx.x;
    if (t < k * HH) {
        int r = t >> 5, c = t & 31;
        int p = perm[r];
        out[t] = h[(size_t)p * HH + c] * score[p];
    }
}

__global__ void scatter_add_k(float* __restrict__ dst, const float* __restrict__ src,
                              const int* __restrict__ perm, int k) {
    int t = blockIdx.x * blockDim.x + threadIdx.x;
    if (t < k * HH) {
        int r = t >> 5, c = t & 31;
        dst[(size_t)perm[r] * HH + c] += src[t];
    }
}

__global__ void logsoftmax_k(const float* __restrict__ X, float* __restrict__ out, int n) {
    int r = blockIdx.x * blockDim.x + threadIdx.x;
    if (r < n) {
        const float* xp = X + (size_t)r * CC;
        float m = -1e30f;
#pragma unroll
        for (int j = 0; j < CC; j++) m = fmaxf(m, xp[j]);
        float s = 0.f;
#pragma unroll
        for (int j = 0; j < CC; j++) s += expf(xp[j] - m);
        float l = logf(s);
        float* op = out + (size_t)r * CC;
#pragma unroll
        for (int j = 0; j < CC; j++) op[j] = xp[j] - m - l;
    }
}

// ---------------- host side ----------------

static void launch_agg(const float* Am, const float* B, float* C,
                       int M, int N, int K, int mode, const float* dinv,
                       const float* bias, int relu, float* part) {
    int Kchunk, S;
    if (K == 2048)      { Kchunk = 128; S = 16; }
    else if (K == 1024) { Kchunk = 64;  S = 16; }
    else if (K == 512)  { Kchunk = 64;  S = 8; }
    else                { Kchunk = 192; S = (K + 191) / 192; }
    dim3 g(M / 256, S);
    agg_gemm_k<<<g, 256, AGG_SMEM>>>(Am, B, part, M, N, K, Kchunk,
                                     mode == 2 ? dinv : nullptr);
    int tot = M * 32;
    agg_reduce_k<<<(tot + 255) / 256, 256>>>(part, C, B, dinv, bias, M, N, S, mode, relu);
}

static void run_gcn_dense(const float* X, const float* A, int n, int Nout,
                          const float* W, const float* b, int relu, float* out,
                          float* pY, float* part, const float* pdinv) {
    gemm_n32_k<<<(n + 31) / 32, 256>>>(X, W, pY, n, Nout, HH);
    launch_agg(A, pY, out, n, Nout, n, 2, pdinv, b, relu, part);
}

static void run_gcn_sparse(const float* X, int Kin, int Nout,
                           const float* W, const float* b, int relu, float* out,
                           float* pY, float* part, const float* dinv0,
                           const int* rowptr, const int* colidx) {
    if (Kin <= 32)
        gemm_n32_k<<<(NN + 31) / 32, 256>>>(X, W, pY, NN, Nout, Kin);
    else
        launch_agg(X, W, pY, NN, Nout, Kin, 0, nullptr, nullptr, 0, part);
    spmm_gcn_k<<<NN / 8, 256>>>(rowptr, colidx, pY, dinv0, b, out, Nout, relu);
}

extern "C" void kernel_launch(void* const* d_in, const int* in_sizes, int n_in,
                              void* d_out, int out_size) {
    const float* x   = (const float*)d_in[0];
    const int*   ei  = (const int*)d_in[1];
    const float* Wi  = (const float*)d_in[2];
    const float* bi  = (const float*)d_in[3];
    const float* dW  = (const float*)d_in[4];
    const float* db  = (const float*)d_in[5];
    const float* pp  = (const float*)d_in[6];
    const float* uW  = (const float*)d_in[7];
    const float* ub  = (const float*)d_in[8];
    const float* Wf  = (const float*)d_in[9];
    const float* bf  = (const float*)d_in[10];
    float* out = (float*)d_out;

    cudaFuncSetAttribute(pool_aug_s8_k, cudaFuncAttributeMaxDynamicSharedMemorySize, AUG_SMEM);
    cudaFuncSetAttribute(pool_aug_tf32_k, cudaFuncAttributeMaxDynamicSharedMemorySize, AUG_SMEM);
    cudaFuncSetAttribute(agg_gemm_k, cudaFuncAttributeMaxDynamicSharedMemorySize, AGG_SMEM);

    float *pG, *pA1, *pA2, *pA3, *ppart;
    int8_t* pA8;
    float *px0, *pxs0, *pxs1, *pxs2, *phA, *phB, *pY, *pdinv, *pscore;
    int *pperm, *prowptr, *pcolidx, *pdeg;
    cudaGetSymbolAddress((void**)&pA8, g_A8);
    cudaGetSymbolAddress((void**)&pG, g_G);
    cudaGetSymbolAddress((void**)&pA1, g_A1);
    cudaGetSymbolAddress((void**)&pA2, g_A2);
    cudaGetSymbolAddress((void**)&pA3, g_A3);
    cudaGetSymbolAddress((void**)&ppart, g_part);
    cudaGetSymbolAddress((void**)&prowptr, g_rowptr);
    cudaGetSymbolAddress((void**)&pcolidx, g_colidx);
    cudaGetSymbolAddress((void**)&pdeg, g_deg);
    cudaGetSymbolAddress((void**)&px0, g_x0);
    cudaGetSymbolAddress((void**)&pxs0, g_xs0);
    cudaGetSymbolAddress((void**)&pxs1, g_xs1);
    cudaGetSymbolAddress((void**)&pxs2, g_xs2);
    cudaGetSymbolAddress((void**)&phA, g_hA);
    cudaGetSymbolAddress((void**)&phB, g_hB);
    cudaGetSymbolAddress((void**)&pY, g_Y);
    cudaGetSymbolAddress((void**)&pdinv, g_dinv);
    cudaGetSymbolAddress((void**)&pscore, g_score);
    cudaGetSymbolAddress((void**)&pperm, g_perm);

    int* pp0 = pperm;
    int* pp1 = pperm + 2048;
    int* pp2 = pperm + 3072;
    float* dinv0 = pdinv;
    float* dinv1 = pdinv + 4096;
    float* dinv2 = pdinv + 6144;
    float* dinv3 = pdinv + 7168;
    int8_t* pG8 = (int8_t*)pG;

    // ---- build adjacency + CSR + dinv0 ----
    cudaMemsetAsync(pA8, 0, (size_t)NN * NN);
    scatter_edges_k<<<(EE + 255) / 256, 256>>>(ei, pA8);
    degree_dinv_k<<<NN / 8, 256>>>(pA8, pdeg, dinv0);
    prefix_k<<<1, 1024>>>(pdeg, prowptr);
    csr_fill_k<<<NN / 8, 256>>>(pA8, prowptr, pcolidx);

    // ---- x = relu(gcn(x, A, Wi, bi)); h = relu(gcn(x, A, dW0, db0)) ----
    run_gcn_sparse(x, FF, HH, Wi, bi, 1, px0, pY, ppart, dinv0, prowptr, pcolidx);
    run_gcn_sparse(px0, HH, HH, dW, db, 1, pxs0, pY, ppart, dinv0, prowptr, pcolidx);

    // ================= down path =================
    // i = 1 (4096 -> 2048): compact-gather + dense int8 pooled augment
    score_k<<<(NN + 255) / 256, 256>>>(pxs0, pp + 0, pscore, NN);
    sort_topk_k<<<1, 1024>>>(pscore, NN, pp0, 2048);
    gather_h_k<<<(2048 * HH + 255) / 256, 256>>>(pxs0, pp0, pscore, phA, 2048);
    gather_rows_s8_k<<<2048, 256>>>(pA8, pp0, pG8, NN);
    {
        int nt = 2048 / 128;
        pool_aug_s8_k<<<nt * (nt + 1) / 2, 256, AUG_SMEM>>>(pG8, pA1, pp0, 2048, NN);
    }
    rowsum_dinv_k<<<2048, 256>>>(pA1, dinv1, 2048);
    run_gcn_dense(phA, pA1, 2048, HH, dW + 1024, db + 32, 1, pxs1, pY, ppart, dinv1);

    // i = 2 (2048 -> 1024): compact-gather + tf32 pooled augment
    score_k<<<(2048 + 255) / 256, 256>>>(pxs1, pp + 32, pscore, 2048);
    sort_topk_k<<<1, 1024>>>(pscore, 2048, pp1, 1024);
    gather_h_k<<<(1024 * HH + 255) / 256, 256>>>(pxs1, pp1, pscore, phA, 1024);
    gather_rows_f32_k<<<1024, 256>>>(pA1, pp1, pG, 2048);
    {
        int nt = 1024 / 128;
        pool_aug_tf32_k<<<nt * (nt + 1) / 2, 256, AUG_SMEM>>>(pG, pA2, pp1, 1024, 2048);
    }
    rowsum_dinv_k<<<1024, 256>>>(pA2, dinv2, 1024);
    run_gcn_dense(phA, pA2, 1024, HH, dW + 2048, db + 64, 1, pxs2, pY, ppart, dinv2);

    // i = 3 (1024 -> 512): compact-gather + fp32 pooled augment
    score_k<<<(1024 + 255) / 256, 256>>>(pxs2, pp + 64, pscore, 1024);
    sort_topk_k<<<1, 1024>>>(pscore, 1024, pp2, 512);
    gather_h_k<<<(512 * HH + 255) / 256, 256>>>(pxs2, pp2, pscore, phA, 512);
    gather_rows_f32_k<<<512, 256>>>(pA2, pp2, pG, 1024);
    pool_aug_f32_k<<<dim3(512 / 64, 512 / 64), dim3(16, 16)>>>(pG, pA3, pp2, 512, 1024);
    rowsum_dinv_k<<<512, 256>>>(pA3, dinv3, 512);
    run_gcn_dense(phA, pA3, 512, HH, dW + 3072, db + 96, 1, phB, pY, ppart, dinv3);

    // ================= up path =================
    cudaMemcpyAsync(phA, pxs2, (size_t)1024 * HH * sizeof(float), cudaMemcpyDeviceToDevice);
    scatter_add_k<<<(512 * HH + 255) / 256, 256>>>(phA, phB, pp2, 512);
    run_gcn_dense(phA, pA2, 1024, HH, uW, ub, 1, phB, pY, ppart, dinv2);

    cudaMemcpyAsync(phA, pxs1, (size_t)2048 * HH * sizeof(float), cudaMemcpyDeviceToDevice);
    scatter_add_k<<<(1024 * HH + 255) / 256, 256>>>(phA, phB, pp1, 1024);
    run_gcn_dense(phA, pA1, 2048, HH, uW + 1024, ub + 32, 1, phB, pY, ppart, dinv1);

    cudaMemcpyAsync(phA, pxs0, (size_t)NN * HH * sizeof(float), cudaMemcpyDeviceToDevice);
    scatter_add_k<<<(2048 * HH + 255) / 256, 256>>>(phA, phB, pp0, 2048);
    run_gcn_sparse(phA, HH, HH, uW + 2048, ub + 64, 1, phB, pY, ppart, dinv0, prowptr, pcolidx);

    // ---- final gcn + log_softmax ----
    run_gcn_sparse(phB, HH, CC, Wf, bf, 0, phA, pY, ppart, dinv0, prowptr, pcolidx);
    logsoftmax_k<<<(NN + 255) / 256, 256>>>(phA, out, NN);
}

// round 15
// speedup vs baseline: 1.3240x; 1.0034x over previous
#include <cuda_runtime.h>
#include <cuda_bf16.h>
#include <math.h>
#include <stdint.h>

#define NN 4096
#define FF 1433
#define HH 32
#define CC 7
#define EE 131072

// ---------------- device scratch ----------------
__device__ int8_t g_A8[(size_t)NN * NN];
__device__ float g_G[(size_t)NN * NN / 2];
__device__ float g_A1[(size_t)2048 * 2048];
__device__ float g_A2[(size_t)1024 * 1024];
__device__ float g_A3[(size_t)512 * 512];
__device__ float g_part[(size_t)32 * 4096 * 32];
__device__ int   g_rowptr[NN + 1];
__device__ int   g_colidx[2 * EE];
__device__ int   g_deg[NN];
__device__ float g_x0[NN * HH];
__device__ float g_xs0[NN * HH];
__device__ float g_xs1[2048 * HH];
__device__ float g_xs2[1024 * HH];
__device__ float g_hA[NN * HH];
__device__ float g_hB[NN * HH];
__device__ float g_Y[NN * HH];
__device__ float g_dinv[8192];
__device__ float g_score[NN];
__device__ int   g_perm[NN];

#define S8STRIDE 144
#define ASTRIDE 36
#define CSTRIDE 129
#define BUFSZ 18432
#define AUG_SMEM (4 * BUFSZ + 512)

#define CP_ASYNC16(dst, src) \
    asm volatile("cp.async.cg.shared.global [%0], [%1], 16;" :: "r"(dst), "l"(src))
#define CP_COMMIT() asm volatile("cp.async.commit_group;" ::: "memory")
#define CP_WAIT(n)  asm volatile("cp.async.wait_group %0;" :: "n"(n) : "memory")

// ---------------- level-0 sparse path ----------------

__global__ void scatter_edges_k(const int* __restrict__ ei, int8_t* __restrict__ A8) {
    int e = blockIdx.x * blockDim.x + threadIdx.x;
    if (e < EE) {
        int u = ei[e], v = ei[EE + e];
        if (u != v) {
            A8[(size_t)u * NN + v] = 1;
            A8[(size_t)v * NN + u] = 1;
        }
    }
}

__global__ void degree_dinv_k(const int8_t* __restrict__ A8, int* __restrict__ deg,
                              float* __restrict__ dinv) {
    int warp = (blockIdx.x * blockDim.x + threadIdx.x) >> 5;
    int lane = threadIdx.x & 31;
    if (warp >= NN) return;
    const uchar4* row = (const uchar4*)&A8[(size_t)warp * NN];
    int cnt = 0;
    for (int it = lane; it < NN / 4; it += 32) {
        uchar4 v = row[it];
        cnt += (v.x != 0) + (v.y != 0) + (v.z != 0) + (v.w != 0);
    }
#pragma unroll
    for (int o = 16; o > 0; o >>= 1) cnt += __shfl_down_sync(0xffffffffu, cnt, o);
    if (lane == 0) {
        deg[warp] = cnt;
        dinv[warp] = rsqrtf((float)cnt + 2.0f);
    }
}

__global__ void prefix_k(const int* __restrict__ deg, int* __restrict__ rowptr) {
    __shared__ int part[1024];
    int tid = threadIdx.x;
    int base = tid * 4;
    int d0 = deg[base], d1 = deg[base + 1], d2 = deg[base + 2], d3 = deg[base + 3];
    int s = d0 + d1 + d2 + d3;
    part[tid] = s;
    __syncthreads();
    for (int o = 1; o < 1024; o <<= 1) {
        int v = (tid >= o) ? part[tid - o] : 0;
        __syncthreads();
        part[tid] += v;
        __syncthreads();
    }
    int excl = (tid == 0) ? 0 : part[tid - 1];
    rowptr[base]     = excl;
    rowptr[base + 1] = excl + d0;
    rowptr[base + 2] = excl + d0 + d1;
    rowptr[base + 3] = excl + d0 + d1 + d2;
    if (tid == 1023) rowptr[4096] = part[1023];
}

__global__ void csr_fill_k(const int8_t* __restrict__ A8, const int* __restrict__ rowptr,
                           int* __restrict__ colidx) {
    int warp = (blockIdx.x * blockDim.x + threadIdx.x) >> 5;
    int lane = threadIdx.x & 31;
    if (warp >= NN) return;
    const int8_t* row = &A8[(size_t)warp * NN];
    int pos = rowptr[warp];
    for (int c0 = 0; c0 < NN; c0 += 128) {
        uint32_t w = *(const uint32_t*)&row[c0 + lane * 4];
        int b0 = (w & 0xffu) != 0, b1 = (w & 0xff00u) != 0;
        int b2 = (w & 0xff0000u) != 0, b3 = (w & 0xff000000u) != 0;
        int cnt = b0 + b1 + b2 + b3;
        int inc = cnt;
#pragma unroll
        for (int o = 1; o < 32; o <<= 1) {
            int v = __shfl_up_sync(0xffffffffu, inc, o);
            if (lane >= o) inc += v;
        }
        int excl = inc - cnt;
        int total = __shfl_sync(0xffffffffu, inc, 31);
        int wr = pos + excl;
        int cb = c0 + lane * 4;
        if (b0) colidx[wr++] = cb;
        if (b1) colidx[wr++] = cb + 1;
        if (b2) colidx[wr++] = cb + 2;
        if (b3) colidx[wr++] = cb + 3;
        pos += total;
    }
}

__global__ void spmm_gcn_k(const int* __restrict__ rowptr, const int* __restrict__ colidx,
                           const float* __restrict__ Y, const float* __restrict__ dinv,
                           const float* __restrict__ bias, float* __restrict__ out,
                           int N, int relu) {
    int warp = (blockIdx.x * blockDim.x + threadIdx.x) >> 5;
    int lane = threadIdx.x & 31;
    if (warp >= NN) return;
    int s = rowptr[warp], e = rowptr[warp + 1];
    float acc = 0.f;
    bool act = lane < N;
    for (int base = s; base < e; base += 32) {
        int idx = (base + lane < e) ? colidx[base + lane] : 0;
        int cnt = min(32, e - base);
        int t = 0;
        for (; t + 8 <= cnt; t += 8) {
            float v[8];
#pragma unroll
            for (int q = 0; q < 8; q++) {
                int j = __shfl_sync(0xffffffffu, idx, t + q);
                v[q] = act ? dinv[j] * Y[(size_t)j * N + lane] : 0.f;
            }
#pragma unroll
            for (int q = 0; q < 8; q++) acc += v[q];
        }
        for (; t < cnt; t++) {
            int j = __shfl_sync(0xffffffffu, idx, t);
            if (act) acc += dinv[j] * Y[(size_t)j * N + lane];
        }
    }
    if (act) {
        float dr = dinv[warp];
        float v = dr * (acc + 2.0f * dr * Y[(size_t)warp * N + lane]) + bias[lane];
        if (relu) v = fmaxf(v, 0.0f);
        out[(size_t)warp * N + lane] = v;
    }
}

// ---------------- split-K aggregate GEMM ----------------
#define SAOFF (192 * 32)
#define AGG_SMEM ((192 * 32 + 256 * 33) * 4)

__global__ void __launch_bounds__(256) agg_gemm_k(
    const float* __restrict__ A, const float* __restrict__ B,
    float* __restrict__ part, int M, int N, int K, int Kchunk,
    const float* __restrict__ dinv)
{
    extern __shared__ float sm[];
    float* sB = sm;
    float* sA = sm + SAOFF;

    int tid = threadIdx.x;
    int warp = tid >> 5, lane = tid & 31;
    int myrow = warp * 32 + lane;
    int m0 = blockIdx.x * 256;
    int kc = blockIdx.y * Kchunk;
    bool K4 = (K & 3) == 0;

    for (int i = tid; i < Kchunk * 32; i += 256) {
        int k = i >> 5, c = i & 31;
        int gk = kc + k;
        float bv = 0.f;
        if (gk < K && c < N) {
            bv = B[(size_t)gk * N + c];
            if (dinv) bv *= dinv[gk];
        }
        sB[k * 32 + c] = bv;
    }

    float acc[32];
#pragma unroll
    for (int i = 0; i < 32; i++) acc[i] = 0.f;

    int ksteps = Kchunk >> 5;
    float pv[32];

#define LOADPV(KS) do { \
        int _ks = (KS); \
        _Pragma("unroll") \
        for (int q = 0; q < 8; q++) { \
            int idx = tid + q * 256; \
            int row = idx >> 3, c4 = idx & 7; \
            int gk = kc + _ks * 32 + c4 * 4; \
            const float* ap = &A[(size_t)(m0 + row) * K + gk]; \
            if (K4) { \
                float4 v = (gk < K) ? *(const float4*)ap : make_float4(0, 0, 0, 0); \
                pv[q * 4 + 0] = v.x; pv[q * 4 + 1] = v.y; \
                pv[q * 4 + 2] = v.z; pv[q * 4 + 3] = v.w; \
            } else { \
                _Pragma("unroll") \
                for (int i = 0; i < 4; i++) \
                    pv[q * 4 + i] = (gk + i < K) ? ap[i] : 0.f; \
            } \
        } \
    } while (0)

    LOADPV(0);

    for (int ks = 0; ks < ksteps; ks++) {
        __syncthreads();
#pragma unroll
        for (int q = 0; q < 8; q++) {
            int idx = tid + q * 256;
            int row = idx >> 3, c4 = idx & 7;
#pragma unroll
            for (int i = 0; i < 4; i++)
                sA[row * 33 + c4 * 4 + i] = pv[q * 4 + i];
        }
        __syncthreads();
        if (ks + 1 < ksteps) LOADPV(ks + 1);
#pragma unroll
        for (int kk = 0; kk < 32; kk++) {
            float a = sA[myrow * 33 + kk];
            const float4* bp = (const float4*)&sB[(ks * 32 + kk) * 32];
#pragma unroll
            for (int c4 = 0; c4 < 8; c4++) {
                float4 b = bp[c4];
                acc[c4 * 4 + 0] += a * b.x;
                acc[c4 * 4 + 1] += a * b.y;
                acc[c4 * 4 + 2] += a * b.z;
                acc[c4 * 4 + 3] += a * b.w;
            }
        }
    }

    float* pp = &part[(size_t)blockIdx.y * M * 32 + (size_t)(m0 + myrow) * 32];
#pragma unroll
    for (int c4 = 0; c4 < 8; c4++) {
        float4 v = make_float4(acc[c4 * 4], acc[c4 * 4 + 1], acc[c4 * 4 + 2], acc[c4 * 4 + 3]);
        *(float4*)&pp[c4 * 4] = v;
    }
}

__global__ void agg_reduce_k(const float* __restrict__ part, float* __restrict__ C,
                             const float* __restrict__ Y, const float* __restrict__ dinv,
                             const float* __restrict__ bias, int M, int N, int S,
                             int mode, int relu) {
    int t = blockIdx.x * blockDim.x + threadIdx.x;
    if (t >= M * 32) return;
    int r = t >> 5, c = t & 31;
    float s = 0.f;
    for (int i = 0; i < S; i++) s += part[(size_t)i * M * 32 + t];
    if (c < N) {
        float v = s;
        if (mode == 2) {
            float dr = dinv[r];
            v = dr * (v + 2.0f * dr * Y[(size_t)r * N + c]) + bias[c];
        }
        if (relu) v = fmaxf(v, 0.0f);
        C[(size_t)r * N + c] = v;
    }
}

// ---------------- fused pool+augment (cp.async pipelined, compact G) ----------------

__global__ void __launch_bounds__(256, 2) pool_aug_s8_k(const int8_t* __restrict__ G,
                                                        float* __restrict__ C,
                                                        const int* __restrict__ perm,
                                                        int k, int n) {
    extern __shared__ __align__(16) char smem[];
    float* sC = (float*)smem;
    int* spm = (int*)(smem + 4 * BUFSZ);
    uint32_t sbase = (uint32_t)__cvta_generic_to_shared(smem);

    int tid = threadIdx.x;
    int wid = tid >> 5, lane = tid & 31;
    int wm = wid >> 2, wn = wid & 3;
    int lr = lane >> 2, lc = lane & 3;

    int t = blockIdx.x;
    int by = (int)((sqrtf(8.0f * (float)t + 1.0f) - 1.0f) * 0.5f);
    while ((by + 1) * (by + 2) / 2 <= t) by++;
    while (by * (by + 1) / 2 > t) by--;
    int bx = t - by * (by + 1) / 2;
    int m0 = by * 128, n0 = bx * 128;

    int acc[4][4][4];
#pragma unroll
    for (int i = 0; i < 4; i++)
#pragma unroll
        for (int j = 0; j < 4; j++)
#pragma unroll
            for (int q = 0; q < 4; q++) acc[i][j][q] = 0;

    int nch = n >> 7;
#pragma unroll
    for (int q = 0; q < 4; q++) {
        int idx = tid + q * 256;
        int row = idx >> 3, s = idx & 7;
        CP_ASYNC16(sbase + row * S8STRIDE + s * 16,
                   &G[(size_t)(m0 + row) * n + s * 16]);
        CP_ASYNC16(sbase + 2 * BUFSZ + row * S8STRIDE + s * 16,
                   &G[(size_t)(n0 + row) * n + s * 16]);
    }
    CP_COMMIT();

    for (int ch = 0; ch < nch; ch++) {
        int b = ch & 1;
        if (ch + 1 < nch) {
            int k0 = (ch + 1) << 7;
            int nb = (ch + 1) & 1;
#pragma unroll
            for (int q = 0; q < 4; q++) {
                int idx = tid + q * 256;
                int row = idx >> 3, s = idx & 7;
                CP_ASYNC16(sbase + nb * BUFSZ + row * S8STRIDE + s * 16,
                           &G[(size_t)(m0 + row) * n + k0 + s * 16]);
                CP_ASYNC16(sbase + (2 + nb) * BUFSZ + row * S8STRIDE + s * 16,
                           &G[(size_t)(n0 + row) * n + k0 + s * 16]);
            }
            CP_COMMIT();
            CP_WAIT(1);
        } else {
            CP_WAIT(0);
        }
        __syncthreads();
        int8_t* sA = (int8_t*)smem + b * BUFSZ;
        int8_t* sB = (int8_t*)smem + (2 + b) * BUFSZ;
#pragma unroll
        for (int kt = 0; kt < 4; kt++) {
            int kk = kt * 32;
            uint32_t a[4][4];
#pragma unroll
            for (int i = 0; i < 4; i++) {
                int r0 = wm * 64 + i * 16;
                a[i][0] = *(const uint32_t*)&sA[(r0 + lr) * S8STRIDE + kk + lc * 4];
                a[i][1] = *(const uint32_t*)&sA[(r0 + lr + 8) * S8STRIDE + kk + lc * 4];
                a[i][2] = *(const uint32_t*)&sA[(r0 + lr) * S8STRIDE + kk + lc * 4 + 16];
                a[i][3] = *(const uint32_t*)&sA[(r0 + lr + 8) * S8STRIDE + kk + lc * 4 + 16];
            }
#pragma unroll
            for (int j = 0; j < 4; j++) {
                int c0 = wn * 32 + j * 8;
                uint32_t b0 = *(const uint32_t*)&sB[(c0 + lr) * S8STRIDE + kk + lc * 4];
                uint32_t b1 = *(const uint32_t*)&sB[(c0 + lr) * S8STRIDE + kk + lc * 4 + 16];
#pragma unroll
                for (int i = 0; i < 4; i++) {
                    asm volatile(
                        "mma.sync.aligned.m16n8k32.row.col.s32.s8.s8.s32 "
                        "{%0,%1,%2,%3}, {%4,%5,%6,%7}, {%8,%9}, {%0,%1,%2,%3};"
                        : "+r"(acc[i][j][0]), "+r"(acc[i][j][1]),
                          "+r"(acc[i][j][2]), "+r"(acc[i][j][3])
                        : "r"(a[i][0]), "r"(a[i][1]), "r"(a[i][2]), "r"(a[i][3]),
                          "r"(b0), "r"(b1));
                }
            }
        }
        __syncthreads();
    }

    if (tid < 128) spm[tid] = perm[n0 + tid];
#pragma unroll
    for (int i = 0; i < 4; i++) {
#pragma unroll
        for (int j = 0; j < 4; j++) {
            int r0 = wm * 64 + i * 16 + lr;
            int c0 = wn * 32 + j * 8 + 2 * lc;
            sC[r0 * CSTRIDE + c0]           = (float)acc[i][j][0];
            sC[r0 * CSTRIDE + c0 + 1]       = (float)acc[i][j][1];
            sC[(r0 + 8) * CSTRIDE + c0]     = (float)acc[i][j][2];
            sC[(r0 + 8) * CSTRIDE + c0 + 1] = (float)acc[i][j][3];
        }
    }
    __syncthreads();

    for (int e = tid; e < 128 * 128; e += 256) {
        int r = e >> 7, c = e & 127;
        float v = sC[r * CSTRIDE + c] + 2.0f * (float)G[(size_t)(m0 + r) * n + spm[c]];
        if (m0 + r == n0 + c) v = 0.0f;
        C[(size_t)(m0 + r) * k + n0 + c] = v;
        sC[r * CSTRIDE + c] = v;
    }
    __syncthreads();
    if (bx != by) {
        for (int e = tid; e < 128 * 128; e += 256) {
            int r = e >> 7, c = e & 127;
            C[(size_t)(n0 + r) * k + m0 + c] = sC[c * CSTRIDE + r];
        }
    }
}

__global__ void __launch_bounds__(256, 2) pool_aug_tf32_k(const float* __restrict__ G,
                                                          float* __restrict__ C,
                                                          const int* __restrict__ perm,
                                                          int k, int n) {
    extern __shared__ __align__(16) char smem[];
    float* sC = (float*)smem;
    int* spm = (int*)(smem + 4 * BUFSZ);
    uint32_t sbase = (uint32_t)__cvta_generic_to_shared(smem);

    int tid = threadIdx.x;
    int wid = tid >> 5, lane = tid & 31;
    int wm = wid >> 2, wn = wid & 3;
    int lr = lane >> 2, lc = lane & 3;

    int t = blockIdx.x;
    int by = (int)((sqrtf(8.0f * (float)t + 1.0f) - 1.0f) * 0.5f);
    while ((by + 1) * (by + 2) / 2 <= t) by++;
    while (by * (by + 1) / 2 > t) by--;
    int bx = t - by * (by + 1) / 2;
    int m0 = by * 128, n0 = bx * 128;

    float acc[4][4][4];
#pragma unroll
    for (int i = 0; i < 4; i++)
#pragma unroll
        for (int j = 0; j < 4; j++)
#pragma unroll
            for (int q = 0; q < 4; q++) acc[i][j][q] = 0.f;

    int nch = n >> 5;
#pragma unroll
    for (int q = 0; q < 4; q++) {
        int idx = tid + q * 256;
        int row = idx >> 3, c4 = idx & 7;
        CP_ASYNC16(sbase + (row * ASTRIDE + c4 * 4) * 4,
                   &G[(size_t)(m0 + row) * n + c4 * 4]);
        CP_ASYNC16(sbase + 2 * BUFSZ + (row * ASTRIDE + c4 * 4) * 4,
                   &G[(size_t)(n0 + row) * n + c4 * 4]);
    }
    CP_COMMIT();

    for (int ch = 0; ch < nch; ch++) {
        int b = ch & 1;
        if (ch + 1 < nch) {
            int k0 = (ch + 1) << 5;
            int nb = (ch + 1) & 1;
#pragma unroll
            for (int q = 0; q < 4; q++) {
                int idx = tid + q * 256;
                int row = idx >> 3, c4 = idx & 7;
                CP_ASYNC16(sbase + nb * BUFSZ + (row * ASTRIDE + c4 * 4) * 4,
                           &G[(size_t)(m0 + row) * n + k0 + c4 * 4]);
                CP_ASYNC16(sbase + (2 + nb) * BUFSZ + (row * ASTRIDE + c4 * 4) * 4,
                           &G[(size_t)(n0 + row) * n + k0 + c4 * 4]);
            }
            CP_COMMIT();
            CP_WAIT(1);
        } else {
            CP_WAIT(0);
        }
        __syncthreads();
        float* sA = (float*)(smem + b * BUFSZ);
        float* sB = (float*)(smem + (2 + b) * BUFSZ);
#pragma unroll
        for (int kt = 0; kt < 4; kt++) {
            int kk = kt * 8;
            uint32_t a[4][4];
#pragma unroll
            for (int i = 0; i < 4; i++) {
                int r0 = wm * 64 + i * 16;
                a[i][0] = __float_as_uint(sA[(r0 + lr) * ASTRIDE + kk + lc]);
                a[i][1] = __float_as_uint(sA[(r0 + lr + 8) * ASTRIDE + kk + lc]);
                a[i][2] = __float_as_uint(sA[(r0 + lr) * ASTRIDE + kk + lc + 4]);
                a[i][3] = __float_as_uint(sA[(r0 + lr + 8) * ASTRIDE + kk + lc + 4]);
            }
#pragma unroll
            for (int j = 0; j < 4; j++) {
                int c0 = wn * 32 + j * 8;
                uint32_t b0 = __float_as_uint(sB[(c0 + lr) * ASTRIDE + kk + lc]);
                uint32_t b1 = __float_as_uint(sB[(c0 + lr) * ASTRIDE + kk + lc + 4]);
#pragma unroll
                for (int i = 0; i < 4; i++) {
                    asm volatile(
                        "mma.sync.aligned.m16n8k8.row.col.f32.tf32.tf32.f32 "
                        "{%0,%1,%2,%3}, {%4,%5,%6,%7}, {%8,%9}, {%0,%1,%2,%3};"
                        : "+f"(acc[i][j][0]), "+f"(acc[i][j][1]),
                          "+f"(acc[i][j][2]), "+f"(acc[i][j][3])
                        : "r"(a[i][0]), "r"(a[i][1]), "r"(a[i][2]), "r"(a[i][3]),
                          "r"(b0), "r"(b1));
                }
            }
        }
        __syncthreads();
    }

    if (tid < 128) spm[tid] = perm[n0 + tid];
#pragma unroll
    for (int i = 0; i < 4; i++) {
#pragma unroll
        for (int j = 0; j < 4; j++) {
            int r0 = wm * 64 + i * 16 + lr;
            int c0 = wn * 32 + j * 8 + 2 * lc;
            sC[r0 * CSTRIDE + c0]           = acc[i][j][0];
            sC[r0 * CSTRIDE + c0 + 1]       = acc[i][j][1];
            sC[(r0 + 8) * CSTRIDE + c0]     = acc[i][j][2];
            sC[(r0 + 8) * CSTRIDE + c0 + 1] = acc[i][j][3];
        }
    }
    __syncthreads();

    for (int e = tid; e < 128 * 128; e += 256) {
        int r = e >> 7, c = e & 127;
        float v = sC[r * CSTRIDE + c] + 2.0f * G[(size_t)(m0 + r) * n + spm[c]];
        if (m0 + r == n0 + c) v = 0.0f;
        C[(size_t)(m0 + r) * k + n0 + c] = v;
        sC[r * CSTRIDE + c] = v;
    }
    __syncthreads();
    if (bx != by) {
        for (int e = tid; e < 128 * 128; e += 256) {
            int r = e >> 7, c = e & 127;
            C[(size_t)(n0 + r) * k + m0 + c] = sC[c * CSTRIDE + r];
        }
    }
}

__global__ void pool_aug_f32_k(const float* __restrict__ G, float* __restrict__ C,
                               const int* __restrict__ perm, int k, int n) {
    __shared__ __align__(16) float As[16][68];
    __shared__ __align__(16) float Bs[16][68];
    __shared__ int spm[64];
    int tx = threadIdx.x, ty = threadIdx.y;
    int t = ty * 16 + tx;
    int m0 = blockIdx.y * 64, n0 = blockIdx.x * 64;
    float acc[4][4] = {};

    if (t < 64) spm[t] = perm[n0 + t];

    for (int k0 = 0; k0 < n; k0 += 16) {
#pragma unroll
        for (int q = 0; q < 4; q++) {
            int idx = t + q * 256;
            int m = idx >> 4, kk = idx & 15;
            As[kk][m] = G[(size_t)(m0 + m) * n + k0 + kk];
            Bs[kk][m] = G[(size_t)(n0 + m) * n + k0 + kk];
        }
        __syncthreads();
#pragma unroll
        for (int kk = 0; kk < 16; kk++) {
            float4 a4 = *(const float4*)&As[kk][ty * 4];
            float4 b4 = *(const float4*)&Bs[kk][tx * 4];
            float a[4] = {a4.x, a4.y, a4.z, a4.w};
            float b[4] = {b4.x, b4.y, b4.z, b4.w};
#pragma unroll
            for (int i = 0; i < 4; i++)
#pragma unroll
                for (int j = 0; j < 4; j++) acc[i][j] += a[i] * b[j];
        }
        __syncthreads();
    }

#pragma unroll
    for (int i = 0; i < 4; i++) {
        int r = m0 + ty * 4 + i;
#pragma unroll
        for (int j = 0; j < 4; j++) {
            int c = n0 + tx * 4 + j;
            float v = acc[i][j] + 2.0f * G[(size_t)r * n + spm[tx * 4 + j]];
            if (r == c) v = 0.0f;
            C[(size_t)r * k + c] = v;
        }
    }
}

// ---------------- simple kernels ----------------

__global__ void rowsum_dinv_k(const float* __restrict__ A, float* __restrict__ dinv, int n) {
    __shared__ float sm[256];
    int row = blockIdx.x;
    float s = 0.f;
    const float* rp = A + (size_t)row * n;
    for (int j = threadIdx.x; j < n; j += 256) s += rp[j];
    sm[threadIdx.x] = s;
    __syncthreads();
    for (int o = 128; o > 0; o >>= 1) {
        if (threadIdx.x < o) sm[threadIdx.x] += sm[threadIdx.x + o];
        __syncthreads();
    }
    if (threadIdx.x == 0) dinv[row] = rsqrtf(sm[0] + 2.0f);
}

__global__ void gather_rows_s8_k(const int8_t* __restrict__ A8, const int* __restrict__ perm,
                                 int8_t* __restrict__ G, int n) {
    int row = blockIdx.x;
    int p = perm[row];
    const int4* src = (const int4*)&A8[(size_t)p * n];
    int4* dst = (int4*)&G[(size_t)row * n];
    for (int i = threadIdx.x; i < n / 16; i += 256) dst[i] = src[i];
}

__global__ void gather_rows_f32_k(const float* __restrict__ A, const int* __restrict__ perm,
                                  float* __restrict__ G, int n) {
    int row = blockIdx.x;
    int p = perm[row];
    const float4* src = (const float4*)&A[(size_t)p * n];
    float4* dst = (float4*)&G[(size_t)row * n];
    for (int i = threadIdx.x; i < n / 4; i += 256) dst[i] = src[i];
}

__global__ void gemm_n32_k(const float* __restrict__ A, const float* __restrict__ B,
                           float* __restrict__ C, int M, int N, int K) {
    __shared__ __align__(16) float As[32][33];
    __shared__ __align__(16) float Bs[32][32];
    int tid = threadIdx.x;
    int m0 = blockIdx.x * 32;
    int r = tid >> 3, cg = (tid & 7) * 4;
    float acc[4] = {};
    for (int k0 = 0; k0 < K; k0 += 32) {
#pragma unroll
        for (int q = 0; q < 4; q++) {
            int e = tid + q * 256;
            int row = e >> 5, col = e & 31;
            int gr = m0 + row, gk = k0 + col;
            As[row][col] = (gr < M && gk < K) ? A[(size_t)gr * K + gk] : 0.f;
            int bk = k0 + row;
            Bs[row][col] = (bk < K && col < N) ? B[(size_t)bk * N + col] : 0.f;
        }
        __syncthreads();
#pragma unroll
        for (int kk = 0; kk < 32; kk++) {
            float a = As[r][kk];
            float4 b = *(const float4*)&Bs[kk][cg];
            acc[0] += a * b.x; acc[1] += a * b.y; acc[2] += a * b.z; acc[3] += a * b.w;
        }
        __syncthreads();
    }
    int gr = m0 + r;
    if (gr < M) {
#pragma unroll
        for (int j = 0; j < 4; j++) {
            int c = cg + j;
            if (c < N) C[(size_t)gr * N + c] = acc[j];
        }
    }
}

__global__ void score_k(const float* __restrict__ h, const float* __restrict__ p,
                        float* __restrict__ score, int n) {
    __shared__ float ps[HH];
    __shared__ float pn;
    if (threadIdx.x < HH) ps[threadIdx.x] = p[threadIdx.x];
    __syncthreads();
    if (threadIdx.x == 0) {
        float s = 0.f;
        for (int i = 0; i < HH; i++) s += ps[i] * ps[i];
        pn = sqrtf(s);
    }
    __syncthreads();
    int i = blockIdx.x * blockDim.x + threadIdx.x;
    if (i < n) {
        float s = 0.f;
        const float* hp = h + (size_t)i * HH;
#pragma unroll
        for (int c = 0; c < HH; c++) s += hp[c] * ps[c];
        score[i] = tanhf(s / pn);
    }
}

__global__ void sort_topk_k(const float* __restrict__ score, int n,
                            int* __restrict__ perm, int k) {
    __shared__ unsigned long long sk[4096];
    int tid = threadIdx.x;
    for (int i = tid; i < n; i += 1024) {
        unsigned u = __float_as_uint(score[i]);
        u = (u & 0x80000000u) ? ~u : (u | 0x80000000u);
        sk[i] = ((unsigned long long)(~u) << 32) | (unsigned)i;
    }
    __syncthreads();
    for (int kk = 2; kk <= n; kk <<= 1) {
        for (int j = kk >> 1; j > 0; j >>= 1) {
            for (int idx = tid; idx < n; idx += 1024) {
                int ixj = idx ^ j;
                if (ixj > idx) {
                    bool up = ((idx & kk) == 0);
                    unsigned long long a = sk[idx], b = sk[ixj];
                    if ((a > b) == up) { sk[idx] = b; sk[ixj] = a; }
                }
            }
            __syncthreads();
        }
    }
    for (int r = tid; r < k; r += 1024) perm[r] = (int)(sk[r] & 0xffffffffULL);
}

__global__ void gather_h_k(const float* __restrict__ h, const int* __restrict__ perm,
                           const float* __restrict__ score, float* __restrict__ out, int k) {
    int t = blockIdx.x * blockDim.x + threadIdx.x;
    if (t < k * HH) {
        int r = t >> 5, c = t & 31;
        int p = perm[r];
        out[t] = h[(size_t)p * HH + c] * score[p];
    }
}

__global__ void scatter_add_k(float* __restrict__ dst, const float* __restrict__ src,
                              const int* __restrict__ perm, int k) {
    int t = blockIdx.x * blockDim.x + threadIdx.x;
    if (t < k * HH) {
        int r = t >> 5, c = t & 31;
        dst[(size_t)perm[r] * HH + c] += src[t];
    }
}

__global__ void logsoftmax_k(const float* __restrict__ X, float* __restrict__ out, int n) {
    int r = blockIdx.x * blockDim.x + threadIdx.x;
    if (r < n) {
        const float* xp = X + (size_t)r * CC;
        float m = -1e30f;
#pragma unroll
        for (int j = 0; j < CC; j++) m = fmaxf(m, xp[j]);
        float s = 0.f;
#pragma unroll
        for (int j = 0; j < CC; j++) s += expf(xp[j] - m);
        float l = logf(s);
        float* op = out + (size_t)r * CC;
#pragma unroll
        for (int j = 0; j < CC; j++) op[j] = xp[j] - m - l;
    }
}

// ---------------- host side ----------------

static void launch_agg(const float* Am, const float* B, float* C,
                       int M, int N, int K, int mode, const float* dinv,
                       const float* bias, int relu, float* part) {
    // occupancy-tuned split-K: target >= ~148 CTAs
    int Kchunk, S;
    if (K == 2048)      { Kchunk = 64;  S = 32; }   // (M/256=8) * 32 = 256 CTAs
    else if (K == 1024) { Kchunk = 32;  S = 32; }   // 4 * 32 = 128 CTAs
    else if (K == 512)  { Kchunk = 32;  S = 16; }   // 2 * 16 = 32 CTAs
    else                { Kchunk = 96;  S = (K + 95) / 96; }  // K=1433: 16*15=240 CTAs
    dim3 g(M / 256, S);
    agg_gemm_k<<<g, 256, AGG_SMEM>>>(Am, B, part, M, N, K, Kchunk,
                                     mode == 2 ? dinv : nullptr);
    int tot = M * 32;
    agg_reduce_k<<<(tot + 255) / 256, 256>>>(part, C, B, dinv, bias, M, N, S, mode, relu);
}

static void run_gcn_dense(const float* X, const float* A, int n, int Nout,
                          const float* W, const float* b, int relu, float* out,
                          float* pY, float* part, const float* pdinv) {
    gemm_n32_k<<<(n + 31) / 32, 256>>>(X, W, pY, n, Nout, HH);
    launch_agg(A, pY, out, n, Nout, n, 2, pdinv, b, relu, part);
}

static void run_gcn_sparse(const float* X, int Kin, int Nout,
                           const float* W, const float* b, int relu, float* out,
                           float* pY, float* part, const float* dinv0,
                           const int* rowptr, const int* colidx) {
    if (Kin <= 32)
        gemm_n32_k<<<(NN + 31) / 32, 256>>>(X, W, pY, NN, Nout, Kin);
    else
        launch_agg(X, W, pY, NN, Nout, Kin, 0, nullptr, nullptr, 0, part);
    spmm_gcn_k<<<NN / 8, 256>>>(rowptr, colidx, pY, dinv0, b, out, Nout, relu);
}

extern "C" void kernel_launch(void* const* d_in, const int* in_sizes, int n_in,
                              void* d_out, int out_size) {
    const float* x   = (const float*)d_in[0];
    const int*   ei  = (const int*)d_in[1];
    const float* Wi  = (const float*)d_in[2];
    const float* bi  = (const float*)d_in[3];
    const float* dW  = (const float*)d_in[4];
    const float* db  = (const float*)d_in[5];
    const float* pp  = (const float*)d_in[6];
    const float* uW  = (const float*)d_in[7];
    const float* ub  = (const float*)d_in[8];
    const float* Wf  = (const float*)d_in[9];
    const float* bf  = (const float*)d_in[10];
    float* out = (float*)d_out;

    cudaFuncSetAttribute(pool_aug_s8_k, cudaFuncAttributeMaxDynamicSharedMemorySize, AUG_SMEM);
    cudaFuncSetAttribute(pool_aug_tf32_k, cudaFuncAttributeMaxDynamicSharedMemorySize, AUG_SMEM);
    cudaFuncSetAttribute(agg_gemm_k, cudaFuncAttributeMaxDynamicSharedMemorySize, AGG_SMEM);

    float *pG, *pA1, *pA2, *pA3, *ppart;
    int8_t* pA8;
    float *px0, *pxs0, *pxs1, *pxs2, *phA, *phB, *pY, *pdinv, *pscore;
    int *pperm, *prowptr, *pcolidx, *pdeg;
    cudaGetSymbolAddress((void**)&pA8, g_A8);
    cudaGetSymbolAddress((void**)&pG, g_G);
    cudaGetSymbolAddress((void**)&pA1, g_A1);
    cudaGetSymbolAddress((void**)&pA2, g_A2);
    cudaGetSymbolAddress((void**)&pA3, g_A3);
    cudaGetSymbolAddress((void**)&ppart, g_part);
    cudaGetSymbolAddress((void**)&prowptr, g_rowptr);
    cudaGetSymbolAddress((void**)&pcolidx, g_colidx);
    cudaGetSymbolAddress((void**)&pdeg, g_deg);
    cudaGetSymbolAddress((void**)&px0, g_x0);
    cudaGetSymbolAddress((void**)&pxs0, g_xs0);
    cudaGetSymbolAddress((void**)&pxs1, g_xs1);
    cudaGetSymbolAddress((void**)&pxs2, g_xs2);
    cudaGetSymbolAddress((void**)&phA, g_hA);
    cudaGetSymbolAddress((void**)&phB, g_hB);
    cudaGetSymbolAddress((void**)&pY, g_Y);
    cudaGetSymbolAddress((void**)&pdinv, g_dinv);
    cudaGetSymbolAddress((void**)&pscore, g_score);
    cudaGetSymbolAddress((void**)&pperm, g_perm);

    int* pp0 = pperm;
    int* pp1 = pperm + 2048;
    int* pp2 = pperm + 3072;
    float* dinv0 = pdinv;
    float* dinv1 = pdinv + 4096;
    float* dinv2 = pdinv + 6144;
    float* dinv3 = pdinv + 7168;
    int8_t* pG8 = (int8_t*)pG;

    // ---- build adjacency + CSR + dinv0 ----
    cudaMemsetAsync(pA8, 0, (size_t)NN * NN);
    scatter_edges_k<<<(EE + 255) / 256, 256>>>(ei, pA8);
    degree_dinv_k<<<NN / 8, 256>>>(pA8, pdeg, dinv0);
    prefix_k<<<1, 1024>>>(pdeg, prowptr);
    csr_fill_k<<<NN / 8, 256>>>(pA8, prowptr, pcolidx);

    // ---- x = relu(gcn(x, A, Wi, bi)); h = relu(gcn(x, A, dW0, db0)) ----
    run_gcn_sparse(x, FF, HH, Wi, bi, 1, px0, pY, ppart, dinv0, prowptr, pcolidx);
    run_gcn_sparse(px0, HH, HH, dW, db, 1, pxs0, pY, ppart, dinv0, prowptr, pcolidx);

    // ================= down path =================
    // i = 1 (4096 -> 2048): compact-gather + dense int8 pooled augment
    score_k<<<(NN + 255) / 256, 256>>>(pxs0, pp + 0, pscore, NN);
    sort_topk_k<<<1, 1024>>>(pscore, NN, pp0, 2048);
    gather_h_k<<<(2048 * HH + 255) / 256, 256>>>(pxs0, pp0, pscore, phA, 2048);
    gather_rows_s8_k<<<2048, 256>>>(pA8, pp0, pG8, NN);
    {
        int nt = 2048 / 128;
        pool_aug_s8_k<<<nt * (nt + 1) / 2, 256, AUG_SMEM>>>(pG8, pA1, pp0, 2048, NN);
    }
    rowsum_dinv_k<<<2048, 256>>>(pA1, dinv1, 2048);
    run_gcn_dense(phA, pA1, 2048, HH, dW + 1024, db + 32, 1, pxs1, pY, ppart, dinv1);

    // i = 2 (2048 -> 1024): compact-gather + tf32 pooled augment
    score_k<<<(2048 + 255) / 256, 256>>>(pxs1, pp + 32, pscore, 2048);
    sort_topk_k<<<1, 1024>>>(pscore, 2048, pp1, 1024);
    gather_h_k<<<(1024 * HH + 255) / 256, 256>>>(pxs1, pp1, pscore, phA, 1024);
    gather_rows_f32_k<<<1024, 256>>>(pA1, pp1, pG, 2048);
    {
        int nt = 1024 / 128;
        pool_aug_tf32_k<<<nt * (nt + 1) / 2, 256, AUG_SMEM>>>(pG, pA2, pp1, 1024, 2048);
    }
    rowsum_dinv_k<<<1024, 256>>>(pA2, dinv2, 1024);
    run_gcn_dense(phA, pA2, 1024, HH, dW + 2048, db + 64, 1, pxs2, pY, ppart, dinv2);

    // i = 3 (1024 -> 512): compact-gather + fp32 pooled augment
    score_k<<<(1024 + 255) / 256, 256>>>(pxs2, pp + 64, pscore, 1024);
    sort_topk_k<<<1, 1024>>>(pscore, 1024, pp2, 512);
    gather_h_k<<<(512 * HH + 255) / 256, 256>>>(pxs2, pp2, pscore, phA, 512);
    gather_rows_f32_k<<<512, 256>>>(pA2, pp2, pG, 1024);
    pool_aug_f32_k<<<dim3(512 / 64, 512 / 64), dim3(16, 16)>>>(pG, pA3, pp2, 512, 1024);
    rowsum_dinv_k<<<512, 256>>>(pA3, dinv3, 512);
    run_gcn_dense(phA, pA3, 512, HH, dW + 3072, db + 96, 1, phB, pY, ppart, dinv3);

    // ================= up path =================
    cudaMemcpyAsync(phA, pxs2, (size_t)1024 * HH * sizeof(float), cudaMemcpyDeviceToDevice);
    scatter_add_k<<<(512 * HH + 255) / 256, 256>>>(phA, phB, pp2, 512);
    run_gcn_dense(phA, pA2, 1024, HH, uW, ub, 1, phB, pY, ppart, dinv2);

    cudaMemcpyAsync(phA, pxs1, (size_t)2048 * HH * sizeof(float), cudaMemcpyDeviceToDevice);
    scatter_add_k<<<(1024 * HH + 255) / 256, 256>>>(phA, phB, pp1, 1024);
    run_gcn_dense(phA, pA1, 2048, HH, uW + 1024, ub + 32, 1, phB, pY, ppart, dinv1);

    cudaMemcpyAsync(phA, pxs0, (size_t)NN * HH * sizeof(float), cudaMemcpyDeviceToDevice);
    scatter_add_k<<<(2048 * HH + 255) / 256, 256>>>(phA, phB, pp0, 2048);
    run_gcn_sparse(phA, HH, HH, uW + 2048, ub + 64, 1, phB, pY, ppart, dinv0, prowptr, pcolidx);

    // ---- final gcn + log_softmax ----
    run_gcn_sparse(phB, HH, CC, Wf, bf, 0, phA, pY, ppart, dinv0, prowptr, pcolidx);
    logsoftmax_k<<<(NN + 255) / 256, 256>>>(phA, out, NN);
}